// round 4
// baseline (speedup 1.0000x reference)
#include <cuda_runtime.h>
#include <cuda_bf16.h>
#include <cstdint>
#include <cstddef>

// Problem constants
#define BB 4
#define LL 1024
#define CC 256
#define DM 512      // d_model
#define DI 512      // d_inner
#define DS 16       // d_state
#define DR 32       // dt_rank
#define TT (BB*LL)  // 4096 tokens

// ---------------- scratch (__device__ globals: allocation-free) ----------------
__device__ float g_combined[TT*DM];        // (t, 512)
__device__ float g_x0n[TT*CC];             // normalized input0
__device__ float g_weight[TT*CC];          // cw preact -> gate weight
__device__ float g_xz[TT*1024];            // (b,l,e) e in [0,1024)
__device__ float g_u[2][TT*DI];            // conv+silu output, scan-time coords
__device__ float g_xdbl[2][TT*64];         // dt|B|C per token
__device__ float g_delta[2][TT*DI];
__device__ float g_y[2][TT*DI];
__device__ float g_ycomb[TT*DI];
__device__ float g_o1[TT*DI];
__device__ float g_o1n[TT*DI];
__device__ float g_o2[TT*CC];

// ---------------- helpers ----------------
__device__ __forceinline__ float cleanf(float x) {
    if (isnan(x)) return 0.f;
    if (isinf(x)) return x > 0.f ? 1.f : -1.f;
    return x;
}

__device__ __forceinline__ float siluf(float x) {
    return x / (1.f + __expf(-x));
}

// block reduction of two values; NW = number of warps in block
template<int NW>
__device__ __forceinline__ float2 blockReduce2(float a, float b, float* sm) {
    __syncthreads();
    const unsigned full = 0xffffffffu;
    #pragma unroll
    for (int o = 16; o > 0; o >>= 1) {
        a += __shfl_xor_sync(full, a, o);
        b += __shfl_xor_sync(full, b, o);
    }
    int w = threadIdx.x >> 5, ln = threadIdx.x & 31;
    if (ln == 0) { sm[w] = a; sm[NW + w] = b; }
    __syncthreads();
    if (threadIdx.x < 32) {
        a = (ln < NW) ? sm[ln] : 0.f;
        b = (ln < NW) ? sm[NW + ln] : 0.f;
        #pragma unroll
        for (int o = 16; o > 0; o >>= 1) {
            a += __shfl_xor_sync(full, a, o);
            b += __shfl_xor_sync(full, b, o);
        }
        if (ln == 0) { sm[0] = a; sm[1] = b; }
    }
    __syncthreads();
    return make_float2(sm[0], sm[1]);
}

// ---------------- kernel 1: nan_to_num + LN(input0), LN(input1) -> combined ----------------
__global__ void k_ln_inputs(const float* __restrict__ i0, const float* __restrict__ i1,
                            const float* __restrict__ g0, const float* __restrict__ b0,
                            const float* __restrict__ g1, const float* __restrict__ b1) {
    __shared__ float sm[32];
    int t = blockIdx.x, c = threadIdx.x;
    float v0 = cleanf(i0[t*CC + c]);
    float v1 = cleanf(i1[t*CC + c]);
    float2 s0 = blockReduce2<8>(v0, v0*v0, sm);
    float m0 = s0.x * (1.f/CC);
    float var0 = s0.y * (1.f/CC) - m0*m0;
    float x0 = (v0 - m0) * rsqrtf(var0 + 1e-5f) * g0[c] + b0[c];
    g_x0n[t*CC + c] = x0;
    g_combined[t*DM + c] = x0;
    float2 s1 = blockReduce2<8>(v1, v1*v1, sm);
    float m1 = s1.x * (1.f/CC);
    float var1 = s1.y * (1.f/CC) - m1*m1;
    float x1 = (v1 - m1) * rsqrtf(var1 + 1e-5f) * g1[c] + b1[c];
    g_combined[t*DM + CC + c] = x1;
}

// ---------------- generic SGEMM: C[M,N] = A[M,K] * W[N,K]^T (+bias, epilogue) ----------------
// EPI: 0 = store, 1 = +bias, 2 = +bias then softplus
template<int BM, int BN, int BK, int TM, int TN, int EPI>
__global__ void __launch_bounds__((BM/TM)*(BN/TN))
k_gemm(const float* __restrict__ A, int lda,
       const float* __restrict__ W, int ldw,
       const float* __restrict__ bias,
       float* __restrict__ C, int ldc, int K) {
    constexpr int THREADS = (BM/TM)*(BN/TN);
    __shared__ float As[BK][BM + 4];
    __shared__ float Ws[BK][BN + 4];
    const int tid = threadIdx.x;
    const int m0 = blockIdx.y * BM;
    const int n0 = blockIdx.x * BN;
    const int tn = (tid % (BN/TN)) * TN;
    const int tm = (tid / (BN/TN)) * TM;

    float acc[TM][TN];
    #pragma unroll
    for (int i = 0; i < TM; i++)
        #pragma unroll
        for (int j = 0; j < TN; j++) acc[i][j] = 0.f;

    constexpr int A4 = BM*BK/4;
    constexpr int W4 = BN*BK/4;

    for (int k0 = 0; k0 < K; k0 += BK) {
        __syncthreads();
        for (int f = tid; f < A4; f += THREADS) {
            int m = f / (BK/4), kq = f % (BK/4);
            float4 v = *reinterpret_cast<const float4*>(&A[(size_t)(m0+m)*lda + k0 + kq*4]);
            As[kq*4+0][m] = v.x; As[kq*4+1][m] = v.y;
            As[kq*4+2][m] = v.z; As[kq*4+3][m] = v.w;
        }
        for (int f = tid; f < W4; f += THREADS) {
            int n = f / (BK/4), kq = f % (BK/4);
            float4 v = *reinterpret_cast<const float4*>(&W[(size_t)(n0+n)*ldw + k0 + kq*4]);
            Ws[kq*4+0][n] = v.x; Ws[kq*4+1][n] = v.y;
            Ws[kq*4+2][n] = v.z; Ws[kq*4+3][n] = v.w;
        }
        __syncthreads();
        #pragma unroll
        for (int kk = 0; kk < BK; kk++) {
            float ra[TM], rw[TN];
            #pragma unroll
            for (int i = 0; i < TM; i++) ra[i] = As[kk][tm + i];
            #pragma unroll
            for (int j = 0; j < TN; j++) rw[j] = Ws[kk][tn + j];
            #pragma unroll
            for (int i = 0; i < TM; i++)
                #pragma unroll
                for (int j = 0; j < TN; j++)
                    acc[i][j] = fmaf(ra[i], rw[j], acc[i][j]);
        }
    }

    #pragma unroll
    for (int i = 0; i < TM; i++) {
        #pragma unroll
        for (int j = 0; j < TN; j++) {
            float v = acc[i][j];
            if (EPI >= 1) v += bias[n0 + tn + j];
            if (EPI == 2) v = (v > 20.f) ? v : log1pf(__expf(v));
            C[(size_t)(m0 + tm + i)*ldc + n0 + tn + j] = v;
        }
    }
}

// ---------------- kernel 3: LN(cwln) + sigmoid + clip on cw preact (in-place) ----------------
__global__ void k_cwln(const float* __restrict__ g, const float* __restrict__ b) {
    __shared__ float sm[32];
    int t = blockIdx.x, c = threadIdx.x;
    float v = g_weight[t*CC + c];
    float2 s = blockReduce2<8>(v, v*v, sm);
    float m = s.x * (1.f/CC);
    float var = s.y * (1.f/CC) - m*m;
    float x = (v - m) * rsqrtf(var + 1e-5f) * g[c] + b[c];
    float w = 1.f / (1.f + __expf(-x));
    w = fminf(fmaxf(w, 0.01f), 0.99f);
    g_weight[t*CC + c] = w;
}

// ---------------- kernel 5: depthwise causal conv + silu (both directions) ----------------
__global__ void k_conv(const float* __restrict__ cwf, const float* __restrict__ cbf,
                       const float* __restrict__ cwb, const float* __restrict__ cbb) {
    int d = threadIdx.x;            // 0..511
    int b = blockIdx.y;
    int dir = blockIdx.z;
    int t0 = blockIdx.x * 128;
    const float* w = dir ? cwb : cwf;
    float w0 = w[d*4+0], w1 = w[d*4+1], w2 = w[d*4+2], w3 = w[d*4+3];
    float bias = (dir ? cbb : cbf)[d];
    size_t base = (size_t)b * LL;

    auto fetch = [&](int t) -> float {
        if (t < 0) return 0.f;
        int l = dir ? (LL - 1 - t) : t;
        return g_xz[(base + l)*1024 + d];
    };

    float r0 = fetch(t0-3), r1 = fetch(t0-2), r2 = fetch(t0-1);
    float* uo = g_u[dir];
    for (int i = 0; i < 128; i++) {
        int t = t0 + i;
        float x3 = fetch(t);
        float accv = bias + w0*r0 + w1*r1 + w2*r2 + w3*x3;
        uo[(base + t)*DI + d] = siluf(accv);
        r0 = r1; r1 = r2; r2 = x3;
    }
}

// ---------------- kernel 8: selective scan (4 lanes per sequence, 4 states each) ----------------
__global__ void k_scan(const float* __restrict__ Alf, const float* __restrict__ Alb,
                       const float* __restrict__ Df,  const float* __restrict__ Db) {
    int gid = blockIdx.x * blockDim.x + threadIdx.x;   // 16384 threads
    int sg  = gid & 3;            // state group (4 states each)
    int d   = (gid >> 2) & 511;
    int b   = (gid >> 11) & 3;
    int dir = (gid >> 13) & 1;
    const unsigned full = 0xffffffffu;

    const float* Al = dir ? Alb : Alf;
    float a[4];
    #pragma unroll
    for (int n = 0; n < 4; n++) a[n] = -__expf(Al[d*DS + sg*4 + n]);
    float Dv = (dir ? Db : Df)[d];

    const float* dl = g_delta[dir];
    const float* uu = g_u[dir];
    const float* xd = g_xdbl[dir];
    float* yo = g_y[dir];

    float h[4] = {0.f, 0.f, 0.f, 0.f};
    size_t base = (size_t)b * LL;

    for (int t = 0; t < LL; t++) {
        size_t row = base + t;
        size_t idx = row*DI + d;
        float delta = dl[idx];
        float u = uu[idx];
        float du = delta * u;
        float4 Bv = *reinterpret_cast<const float4*>(xd + row*64 + 32 + sg*4);
        float4 Cv = *reinterpret_cast<const float4*>(xd + row*64 + 48 + sg*4);
        float y = 0.f;
        float Ba[4] = {Bv.x, Bv.y, Bv.z, Bv.w};
        float Ca[4] = {Cv.x, Cv.y, Cv.z, Cv.w};
        #pragma unroll
        for (int n = 0; n < 4; n++) {
            float dA = __expf(delta * a[n]);
            h[n] = fmaf(dA, h[n], du * Ba[n]);
            y = fmaf(h[n], Ca[n], y);
        }
        // reduce across the 4 state-group lanes
        y += __shfl_xor_sync(full, y, 1);
        y += __shfl_xor_sync(full, y, 2);
        y = fmaf(Dv, u, y);
        int l = dir ? (LL - 1 - t) : t;
        float z = g_xz[(base + l)*1024 + DI + d];
        y *= siluf(z);
        if (sg == 0) yo[idx] = y;
    }
}

// ---------------- kernel 9: combine directions + mnorm LN ----------------
__global__ void k_combine(const float* __restrict__ g, const float* __restrict__ b_) {
    __shared__ float sm[32];
    int t = blockIdx.x;
    int b = t >> 10, l = t & (LL - 1);
    int d = threadIdx.x;
    float v = 0.5f * (g_y[0][(size_t)t*DI + d] +
                      g_y[1][((size_t)b*LL + (LL - 1 - l))*DI + d]);
    float2 s = blockReduce2<16>(v, v*v, sm);
    float m = s.x * (1.f/DI);
    float var = s.y * (1.f/DI) - m*m;
    g_ycomb[(size_t)t*DI + d] = (v - m) * rsqrtf(var + 1e-5f) * g[d] + b_[d];
}

// ---------------- kernel 11: pnorm LN ----------------
__global__ void k_pnorm(const float* __restrict__ g, const float* __restrict__ b) {
    __shared__ float sm[32];
    int t = blockIdx.x, d = threadIdx.x;
    float v = g_o1[(size_t)t*DM + d];
    float2 s = blockReduce2<16>(v, v*v, sm);
    float m = s.x * (1.f/DM);
    float var = s.y * (1.f/DM) - m*m;
    g_o1n[(size_t)t*DM + d] = (v - m) * rsqrtf(var + 1e-5f) * g[d] + b[d];
}

// ---------------- kernel 13: final blend ----------------
__global__ void k_final(const float* __restrict__ i0, float* __restrict__ out) {
    int idx = blockIdx.x * blockDim.x + threadIdx.x;
    float v = cleanf(g_o2[idx]);
    float w = g_weight[idx];
    out[idx] = v*w + g_x0n[idx]*(1.f - w) + cleanf(i0[idx]);
}

// ---------------- launch ----------------
extern "C" void kernel_launch(void* const* d_in, const int* in_sizes, int n_in,
                              void* d_out, int out_size) {
    const float* input0   = (const float*)d_in[0];
    const float* input1   = (const float*)d_in[1];
    const float* norm0_g  = (const float*)d_in[2];
    const float* norm0_b  = (const float*)d_in[3];
    const float* norm1_g  = (const float*)d_in[4];
    const float* norm1_b  = (const float*)d_in[5];
    const float* in_proj_w= (const float*)d_in[6];

    const float *convf_w, *convf_b, *convb_w, *convb_b;
    const float *xprojf_w, *xprojb_w, *dtf_w, *dtf_b, *dtb_w, *dtb_b;
    const float *A_log_f, *A_log_b, *D_f, *D_b;
    const float *mnorm_g, *mnorm_b, *outproj_w, *pnorm_g, *pnorm_b;
    const float *projback_w, *projback_b, *cw_w, *cw_b, *cwln_g, *cwln_b;

    if (in_sizes[9] == 2048) {
        // reference-signature order:
        // convf_w, convf_b, convb_w, convb_b, xprojf_w, xprojb_w,
        // dtf_w, dtf_b, dtb_w, dtb_b, A_log_f, A_log_b, D_f, D_b, ...
        convf_w    = (const float*)d_in[7];
        convf_b    = (const float*)d_in[8];
        convb_w    = (const float*)d_in[9];
        convb_b    = (const float*)d_in[10];
        xprojf_w   = (const float*)d_in[11];
        xprojb_w   = (const float*)d_in[12];
        dtf_w      = (const float*)d_in[13];
        dtf_b      = (const float*)d_in[14];
        dtb_w      = (const float*)d_in[15];
        dtb_b      = (const float*)d_in[16];
        A_log_f    = (const float*)d_in[17];
        A_log_b    = (const float*)d_in[18];
        D_f        = (const float*)d_in[19];
        D_b        = (const float*)d_in[20];
    } else {
        // setup_inputs dict-insertion order:
        // convf_w, convf_b, xprojf_w, dtf_w, dtf_b, A_log_f, D_f,
        // convb_w, convb_b, xprojb_w, dtb_w, dtb_b, A_log_b, D_b, ...
        convf_w    = (const float*)d_in[7];
        convf_b    = (const float*)d_in[8];
        xprojf_w   = (const float*)d_in[9];
        dtf_w      = (const float*)d_in[10];
        dtf_b      = (const float*)d_in[11];
        A_log_f    = (const float*)d_in[12];
        D_f        = (const float*)d_in[13];
        convb_w    = (const float*)d_in[14];
        convb_b    = (const float*)d_in[15];
        xprojb_w   = (const float*)d_in[16];
        dtb_w      = (const float*)d_in[17];
        dtb_b      = (const float*)d_in[18];
        A_log_b    = (const float*)d_in[19];
        D_b        = (const float*)d_in[20];
    }
    mnorm_g    = (const float*)d_in[21];
    mnorm_b    = (const float*)d_in[22];
    outproj_w  = (const float*)d_in[23];
    pnorm_g    = (const float*)d_in[24];
    pnorm_b    = (const float*)d_in[25];
    projback_w = (const float*)d_in[26];
    projback_b = (const float*)d_in[27];
    cw_w       = (const float*)d_in[28];
    cw_b       = (const float*)d_in[29];
    cwln_g     = (const float*)d_in[30];
    cwln_b     = (const float*)d_in[31];
    float* out = (float*)d_out;

    float *combined, *weight, *xz, *u0, *xdbl0, *delta0, *ycomb, *o1n, *o2;
    cudaGetSymbolAddress((void**)&combined, g_combined);
    cudaGetSymbolAddress((void**)&weight,   g_weight);
    cudaGetSymbolAddress((void**)&xz,       g_xz);
    cudaGetSymbolAddress((void**)&u0,       g_u);
    cudaGetSymbolAddress((void**)&xdbl0,    g_xdbl);
    cudaGetSymbolAddress((void**)&delta0,   g_delta);
    cudaGetSymbolAddress((void**)&ycomb,    g_ycomb);
    cudaGetSymbolAddress((void**)&o1n,      g_o1n);
    cudaGetSymbolAddress((void**)&o2,       g_o2);
    float* o1;
    cudaGetSymbolAddress((void**)&o1, g_o1);
    float* u1     = u0     + (size_t)TT*DI;
    float* xdbl1  = xdbl0  + (size_t)TT*64;
    float* delta1 = delta0 + (size_t)TT*DI;

    // 1. input LayerNorms -> combined, x0n
    k_ln_inputs<<<TT, 256>>>(input0, input1, norm0_g, norm0_b, norm1_g, norm1_b);

    // 2. cw GEMM: (4096x512)@(256x512)^T + bias
    k_gemm<128,64,16,8,4,1><<<dim3(CC/64, TT/128), 256>>>(combined, DM, cw_w, DM, cw_b, weight, CC, DM);
    // 3. cw LN + sigmoid + clip
    k_cwln<<<TT, 256>>>(cwln_g, cwln_b);

    // 4. in_proj GEMM: (4096x512)@(1024x512)^T
    k_gemm<128,64,16,8,4,0><<<dim3(1024/64, TT/128), 256>>>(combined, DM, in_proj_w, DM, nullptr, xz, 1024, DM);

    // 5. conv + silu, both directions
    k_conv<<<dim3(LL/128, BB, 2), 512>>>(convf_w, convf_b, convb_w, convb_b);

    // 6. x_dbl GEMMs: (4096x512)@(64x512)^T
    k_gemm<32,64,16,2,4,0><<<dim3(1, TT/32), 256>>>(u0, DI, xprojf_w, DI, nullptr, xdbl0, 64, DI);
    k_gemm<32,64,16,2,4,0><<<dim3(1, TT/32), 256>>>(u1, DI, xprojb_w, DI, nullptr, xdbl1, 64, DI);

    // 7. delta GEMMs: (4096x32)@(512x32)^T + bias, softplus
    k_gemm<128,64,16,8,4,2><<<dim3(DI/64, TT/128), 256>>>(xdbl0, 64, dtf_w, DR, dtf_b, delta0, DI, DR);
    k_gemm<128,64,16,8,4,2><<<dim3(DI/64, TT/128), 256>>>(xdbl1, 64, dtb_w, DR, dtb_b, delta1, DI, DR);

    // 8. selective scan (both dirs), incl. D*u and silu(z) gate
    k_scan<<<128, 128>>>(A_log_f, A_log_b, D_f, D_b);

    // 9. combine + mnorm
    k_combine<<<TT, 512>>>(mnorm_g, mnorm_b);

    // 10. out_proj GEMM: (4096x512)@(512x512)^T
    k_gemm<128,64,16,8,4,0><<<dim3(DM/64, TT/128), 256>>>(ycomb, DI, outproj_w, DI, nullptr, o1, DM, DI);

    // 11. pnorm
    k_pnorm<<<TT, 512>>>(pnorm_g, pnorm_b);

    // 12. projback GEMM: (4096x512)@(256x512)^T + bias
    k_gemm<128,64,16,8,4,1><<<dim3(CC/64, TT/128), 256>>>(o1n, DM, projback_w, DM, projback_b, o2, CC, DM);

    // 13. final blend
    k_final<<<TT, 256>>>(input0, out);
}

// round 5
// speedup vs baseline: 1.8945x; 1.8945x over previous
#include <cuda_runtime.h>
#include <cuda_bf16.h>
#include <cstdint>
#include <cstddef>

// Problem constants
#define BB 4
#define LL 1024
#define CC 256
#define DM 512      // d_model
#define DI 512      // d_inner
#define DS 16       // d_state
#define DR 32       // dt_rank
#define TT (BB*LL)  // 4096 tokens

// ---------------- scratch (__device__ globals: allocation-free) ----------------
__device__ float g_combined[TT*DM];        // (t, 512)
__device__ float g_x0n[TT*CC];             // normalized input0
__device__ float g_weight[TT*CC];          // cw preact -> gate weight
__device__ float g_xz[TT*1024];            // (b,l,e) e in [0,1024)
__device__ float g_u[2][TT*DI];            // conv+silu output, scan-time coords
__device__ float g_xdbl[2][TT*64];         // dt|B|C per token
__device__ float g_xpart[2][4][TT*64];     // split-K partials for xproj
__device__ float g_delta[2][TT*DI];
__device__ float g_y[2][TT*DI];
__device__ float g_ycomb[TT*DI];
__device__ float g_o1[TT*DI];
__device__ float g_o1n[TT*DI];
__device__ float g_o2[TT*CC];

// ---------------- helpers ----------------
__device__ __forceinline__ float cleanf(float x) {
    if (isnan(x)) return 0.f;
    if (isinf(x)) return x > 0.f ? 1.f : -1.f;
    return x;
}

__device__ __forceinline__ float siluf(float x) {
    return x / (1.f + __expf(-x));
}

// block reduction of two values; NW = number of warps in block
template<int NW>
__device__ __forceinline__ float2 blockReduce2(float a, float b, float* sm) {
    __syncthreads();
    const unsigned full = 0xffffffffu;
    #pragma unroll
    for (int o = 16; o > 0; o >>= 1) {
        a += __shfl_xor_sync(full, a, o);
        b += __shfl_xor_sync(full, b, o);
    }
    int w = threadIdx.x >> 5, ln = threadIdx.x & 31;
    if (ln == 0) { sm[w] = a; sm[NW + w] = b; }
    __syncthreads();
    if (threadIdx.x < 32) {
        a = (ln < NW) ? sm[ln] : 0.f;
        b = (ln < NW) ? sm[NW + ln] : 0.f;
        #pragma unroll
        for (int o = 16; o > 0; o >>= 1) {
            a += __shfl_xor_sync(full, a, o);
            b += __shfl_xor_sync(full, b, o);
        }
        if (ln == 0) { sm[0] = a; sm[1] = b; }
    }
    __syncthreads();
    return make_float2(sm[0], sm[1]);
}

// ---------------- kernel 1: nan_to_num + LN(input0), LN(input1) -> combined ----------------
__global__ void k_ln_inputs(const float* __restrict__ i0, const float* __restrict__ i1,
                            const float* __restrict__ g0, const float* __restrict__ b0,
                            const float* __restrict__ g1, const float* __restrict__ b1) {
    __shared__ float sm[32];
    int t = blockIdx.x, c = threadIdx.x;
    float v0 = cleanf(i0[t*CC + c]);
    float v1 = cleanf(i1[t*CC + c]);
    float2 s0 = blockReduce2<8>(v0, v0*v0, sm);
    float m0 = s0.x * (1.f/CC);
    float var0 = s0.y * (1.f/CC) - m0*m0;
    float x0 = (v0 - m0) * rsqrtf(var0 + 1e-5f) * g0[c] + b0[c];
    g_x0n[t*CC + c] = x0;
    g_combined[t*DM + c] = x0;
    float2 s1 = blockReduce2<8>(v1, v1*v1, sm);
    float m1 = s1.x * (1.f/CC);
    float var1 = s1.y * (1.f/CC) - m1*m1;
    float x1 = (v1 - m1) * rsqrtf(var1 + 1e-5f) * g1[c] + b1[c];
    g_combined[t*DM + CC + c] = x1;
}

// ---------------- SGEMM: C[M,N] = A[M,K] * W[N,K]^T (+bias, epilogue) ----------------
// 8x8 thread tile, 128 threads, BM=128, BN=64, BK=16.
// EPI: 0 = store, 1 = +bias, 2 = +bias then softplus
template<int BM, int BN, int BK, int TM, int TN, int EPI>
__global__ void __launch_bounds__((BM/TM)*(BN/TN))
k_gemm(const float* __restrict__ A, int lda,
       const float* __restrict__ W, int ldw,
       const float* __restrict__ bias,
       float* __restrict__ C, int ldc, int K) {
    constexpr int THREADS = (BM/TM)*(BN/TN);
    __shared__ __align__(16) float As[BK][BM + 4];
    __shared__ __align__(16) float Ws[BK][BN + 4];
    const int tid = threadIdx.x;
    const int m0 = blockIdx.y * BM;
    const int n0 = blockIdx.x * BN;
    const int tn = (tid % (BN/TN)) * TN;
    const int tm = (tid / (BN/TN)) * TM;

    float acc[TM][TN];
    #pragma unroll
    for (int i = 0; i < TM; i++)
        #pragma unroll
        for (int j = 0; j < TN; j++) acc[i][j] = 0.f;

    constexpr int A4 = BM*BK/4;
    constexpr int W4 = BN*BK/4;

    for (int k0 = 0; k0 < K; k0 += BK) {
        __syncthreads();
        #pragma unroll
        for (int f = tid; f < A4; f += THREADS) {
            int m = f / (BK/4), kq = f % (BK/4);
            float4 v = *reinterpret_cast<const float4*>(&A[(size_t)(m0+m)*lda + k0 + kq*4]);
            As[kq*4+0][m] = v.x; As[kq*4+1][m] = v.y;
            As[kq*4+2][m] = v.z; As[kq*4+3][m] = v.w;
        }
        #pragma unroll
        for (int f = tid; f < W4; f += THREADS) {
            int n = f / (BK/4), kq = f % (BK/4);
            float4 v = *reinterpret_cast<const float4*>(&W[(size_t)(n0+n)*ldw + k0 + kq*4]);
            Ws[kq*4+0][n] = v.x; Ws[kq*4+1][n] = v.y;
            Ws[kq*4+2][n] = v.z; Ws[kq*4+3][n] = v.w;
        }
        __syncthreads();
        #pragma unroll
        for (int kk = 0; kk < BK; kk++) {
            float ra[TM], rw[TN];
            #pragma unroll
            for (int i = 0; i < TM; i += 4)
                *reinterpret_cast<float4*>(&ra[i]) =
                    *reinterpret_cast<const float4*>(&As[kk][tm + i]);
            #pragma unroll
            for (int j = 0; j < TN; j += 4)
                *reinterpret_cast<float4*>(&rw[j]) =
                    *reinterpret_cast<const float4*>(&Ws[kk][tn + j]);
            #pragma unroll
            for (int i = 0; i < TM; i++)
                #pragma unroll
                for (int j = 0; j < TN; j++)
                    acc[i][j] = fmaf(ra[i], rw[j], acc[i][j]);
        }
    }

    #pragma unroll
    for (int i = 0; i < TM; i++) {
        #pragma unroll
        for (int j0 = 0; j0 < TN; j0 += 4) {
            float4 v;
            float* vp = &v.x;
            #pragma unroll
            for (int j = 0; j < 4; j++) {
                float x = acc[i][j0+j];
                if (EPI >= 1) x += bias[n0 + tn + j0 + j];
                if (EPI == 2) x = (x > 20.f) ? x : log1pf(__expf(x));
                vp[j] = x;
            }
            *reinterpret_cast<float4*>(&C[(size_t)(m0 + tm + i)*ldc + n0 + tn + j0]) = v;
        }
    }
}

// ---------------- split-K partial GEMM for xproj: K slice per blockIdx.z ----------------
template<int BM, int BN, int BK, int TM, int TN>
__global__ void __launch_bounds__((BM/TM)*(BN/TN))
k_gemm_part(const float* __restrict__ A, int lda,
            const float* __restrict__ W, int ldw,
            float* __restrict__ P, int ldc, int Kslice) {
    constexpr int THREADS = (BM/TM)*(BN/TN);
    __shared__ __align__(16) float As[BK][BM + 4];
    __shared__ __align__(16) float Ws[BK][BN + 4];
    const int tid = threadIdx.x;
    const int m0 = blockIdx.y * BM;
    const int n0 = blockIdx.x * BN;
    const int s  = blockIdx.z;
    const int kb = s * Kslice;
    const int tn = (tid % (BN/TN)) * TN;
    const int tm = (tid / (BN/TN)) * TM;
    float* Pout = P + (size_t)s * (TT*64);

    float acc[TM][TN];
    #pragma unroll
    for (int i = 0; i < TM; i++)
        #pragma unroll
        for (int j = 0; j < TN; j++) acc[i][j] = 0.f;

    constexpr int A4 = BM*BK/4;
    constexpr int W4 = BN*BK/4;

    for (int k0 = kb; k0 < kb + Kslice; k0 += BK) {
        __syncthreads();
        #pragma unroll
        for (int f = tid; f < A4; f += THREADS) {
            int m = f / (BK/4), kq = f % (BK/4);
            float4 v = *reinterpret_cast<const float4*>(&A[(size_t)(m0+m)*lda + k0 + kq*4]);
            As[kq*4+0][m] = v.x; As[kq*4+1][m] = v.y;
            As[kq*4+2][m] = v.z; As[kq*4+3][m] = v.w;
        }
        #pragma unroll
        for (int f = tid; f < W4; f += THREADS) {
            int n = f / (BK/4), kq = f % (BK/4);
            float4 v = *reinterpret_cast<const float4*>(&W[(size_t)(n0+n)*ldw + k0 + kq*4]);
            Ws[kq*4+0][n] = v.x; Ws[kq*4+1][n] = v.y;
            Ws[kq*4+2][n] = v.z; Ws[kq*4+3][n] = v.w;
        }
        __syncthreads();
        #pragma unroll
        for (int kk = 0; kk < BK; kk++) {
            float ra[TM], rw[TN];
            #pragma unroll
            for (int i = 0; i < TM; i += 4)
                *reinterpret_cast<float4*>(&ra[i]) =
                    *reinterpret_cast<const float4*>(&As[kk][tm + i]);
            #pragma unroll
            for (int j = 0; j < TN; j += 4)
                *reinterpret_cast<float4*>(&rw[j]) =
                    *reinterpret_cast<const float4*>(&Ws[kk][tn + j]);
            #pragma unroll
            for (int i = 0; i < TM; i++)
                #pragma unroll
                for (int j = 0; j < TN; j++)
                    acc[i][j] = fmaf(ra[i], rw[j], acc[i][j]);
        }
    }

    #pragma unroll
    for (int i = 0; i < TM; i++)
        #pragma unroll
        for (int j0 = 0; j0 < TN; j0 += 4) {
            float4 v = make_float4(acc[i][j0], acc[i][j0+1], acc[i][j0+2], acc[i][j0+3]);
            *reinterpret_cast<float4*>(&Pout[(size_t)(m0 + tm + i)*ldc + n0 + tn + j0]) = v;
        }
}

// reduce 4 split-K partials for both dirs -> g_xdbl
__global__ void k_xreduce() {
    int i = blockIdx.x * blockDim.x + threadIdx.x;   // 0 .. 2*TT*64
    int dir = (i >= TT*64) ? 1 : 0;
    int j = i - dir * (TT*64);
    float s = (g_xpart[dir][0][j] + g_xpart[dir][1][j])
            + (g_xpart[dir][2][j] + g_xpart[dir][3][j]);
    g_xdbl[dir][j] = s;
}

// ---------------- kernel 3: LN(cwln) + sigmoid + clip on cw preact (in-place) ----------------
__global__ void k_cwln(const float* __restrict__ g, const float* __restrict__ b) {
    __shared__ float sm[32];
    int t = blockIdx.x, c = threadIdx.x;
    float v = g_weight[t*CC + c];
    float2 s = blockReduce2<8>(v, v*v, sm);
    float m = s.x * (1.f/CC);
    float var = s.y * (1.f/CC) - m*m;
    float x = (v - m) * rsqrtf(var + 1e-5f) * g[c] + b[c];
    float w = 1.f / (1.f + __expf(-x));
    w = fminf(fmaxf(w, 0.01f), 0.99f);
    g_weight[t*CC + c] = w;
}

// ---------------- kernel 5: depthwise causal conv + silu (both directions) ----------------
#define CONV_CHUNK 64
__global__ void k_conv(const float* __restrict__ cwf, const float* __restrict__ cbf,
                       const float* __restrict__ cwb, const float* __restrict__ cbb) {
    int d = threadIdx.x;            // 0..511
    int b = blockIdx.y;
    int dir = blockIdx.z;
    int t0 = blockIdx.x * CONV_CHUNK;
    const float* w = dir ? cwb : cwf;
    float w0 = w[d*4+0], w1 = w[d*4+1], w2 = w[d*4+2], w3 = w[d*4+3];
    float bias = (dir ? cbb : cbf)[d];
    size_t base = (size_t)b * LL;

    auto fetch = [&](int t) -> float {
        if (t < 0) return 0.f;
        int l = dir ? (LL - 1 - t) : t;
        return g_xz[(base + l)*1024 + d];
    };

    float r0 = fetch(t0-3), r1 = fetch(t0-2), r2 = fetch(t0-1);
    float* uo = g_u[dir];
    #pragma unroll 4
    for (int i = 0; i < CONV_CHUNK; i++) {
        int t = t0 + i;
        float x3 = fetch(t);
        float accv = bias + w0*r0 + w1*r1 + w2*r2 + w3*x3;
        uo[(base + t)*DI + d] = siluf(accv);
        r0 = r1; r1 = r2; r2 = x3;
    }
}

// ---------------- kernel 8: selective scan v2 ----------------
// 8 lanes per (dir,b,d) entity, 2 states per lane; unroll-4 with register
// double-buffered prefetch. 32768 threads total.
__global__ void k_scan(const float* __restrict__ Alf, const float* __restrict__ Alb,
                       const float* __restrict__ Df,  const float* __restrict__ Db) {
    int gid = blockIdx.x * blockDim.x + threadIdx.x;
    int l   = gid & 7;             // lane within entity -> states l*2, l*2+1
    int d   = (gid >> 3) & 511;
    int b   = (gid >> 12) & 3;
    int dir = (gid >> 14) & 1;
    const unsigned full = 0xffffffffu;

    const float* Al = dir ? Alb : Alf;
    float a0 = -__expf(Al[d*DS + l*2 + 0]);
    float a1 = -__expf(Al[d*DS + l*2 + 1]);
    float Dv = (dir ? Db : Df)[d];

    const float* dl = g_delta[dir];
    const float* uu = g_u[dir];
    const float* xd = g_xdbl[dir];
    float* yo = g_y[dir];

    size_t base = (size_t)b * LL;
    float h0 = 0.f, h1 = 0.f;

    float  cd[4], cu[4], cz[4];
    float2 cB[4], cC[4];
    #pragma unroll
    for (int j = 0; j < 4; j++) {
        size_t row = base + j;
        cd[j] = dl[row*DI + d];
        cu[j] = uu[row*DI + d];
        cB[j] = *reinterpret_cast<const float2*>(xd + row*64 + 32 + l*2);
        cC[j] = *reinterpret_cast<const float2*>(xd + row*64 + 48 + l*2);
        int lq = dir ? (LL - 1 - j) : j;
        cz[j] = g_xz[(base + lq)*1024 + DI + d];
    }

    for (int t0 = 0; t0 < LL; t0 += 4) {
        float  nd[4] = {0,0,0,0}, nu[4] = {0,0,0,0}, nz[4] = {0,0,0,0};
        float2 nB[4] = {}, nC[4] = {};
        if (t0 + 4 < LL) {
            #pragma unroll
            for (int j = 0; j < 4; j++) {
                size_t row = base + t0 + 4 + j;
                nd[j] = dl[row*DI + d];
                nu[j] = uu[row*DI + d];
                nB[j] = *reinterpret_cast<const float2*>(xd + row*64 + 32 + l*2);
                nC[j] = *reinterpret_cast<const float2*>(xd + row*64 + 48 + l*2);
                int lq = dir ? (LL - 1 - (t0 + 4 + j)) : (t0 + 4 + j);
                nz[j] = g_xz[(base + lq)*1024 + DI + d];
            }
        }
        #pragma unroll
        for (int j = 0; j < 4; j++) {
            int t = t0 + j;
            float delta = cd[j], u = cu[j];
            float du = delta * u;
            h0 = fmaf(__expf(delta * a0), h0, du * cB[j].x);
            h1 = fmaf(__expf(delta * a1), h1, du * cB[j].y);
            float y = h0 * cC[j].x + h1 * cC[j].y;
            y += __shfl_xor_sync(full, y, 1);
            y += __shfl_xor_sync(full, y, 2);
            y += __shfl_xor_sync(full, y, 4);
            y = fmaf(Dv, u, y);
            y *= siluf(cz[j]);
            if (l == 0) yo[(base + t)*DI + d] = y;
        }
        #pragma unroll
        for (int j = 0; j < 4; j++) {
            cd[j] = nd[j]; cu[j] = nu[j]; cz[j] = nz[j];
            cB[j] = nB[j]; cC[j] = nC[j];
        }
    }
}

// ---------------- kernel 9: combine directions + mnorm LN ----------------
__global__ void k_combine(const float* __restrict__ g, const float* __restrict__ b_) {
    __shared__ float sm[32];
    int t = blockIdx.x;
    int b = t >> 10, l = t & (LL - 1);
    int d = threadIdx.x;
    float v = 0.5f * (g_y[0][(size_t)t*DI + d] +
                      g_y[1][((size_t)b*LL + (LL - 1 - l))*DI + d]);
    float2 s = blockReduce2<16>(v, v*v, sm);
    float m = s.x * (1.f/DI);
    float var = s.y * (1.f/DI) - m*m;
    g_ycomb[(size_t)t*DI + d] = (v - m) * rsqrtf(var + 1e-5f) * g[d] + b_[d];
}

// ---------------- kernel 11: pnorm LN ----------------
__global__ void k_pnorm(const float* __restrict__ g, const float* __restrict__ b) {
    __shared__ float sm[32];
    int t = blockIdx.x, d = threadIdx.x;
    float v = g_o1[(size_t)t*DM + d];
    float2 s = blockReduce2<16>(v, v*v, sm);
    float m = s.x * (1.f/DM);
    float var = s.y * (1.f/DM) - m*m;
    g_o1n[(size_t)t*DM + d] = (v - m) * rsqrtf(var + 1e-5f) * g[d] + b[d];
}

// ---------------- kernel 13: final blend ----------------
__global__ void k_final(const float* __restrict__ i0, float* __restrict__ out) {
    int idx = blockIdx.x * blockDim.x + threadIdx.x;
    float v = cleanf(g_o2[idx]);
    float w = g_weight[idx];
    out[idx] = v*w + g_x0n[idx]*(1.f - w) + cleanf(i0[idx]);
}

// ---------------- launch ----------------
extern "C" void kernel_launch(void* const* d_in, const int* in_sizes, int n_in,
                              void* d_out, int out_size) {
    const float* input0   = (const float*)d_in[0];
    const float* input1   = (const float*)d_in[1];
    const float* norm0_g  = (const float*)d_in[2];
    const float* norm0_b  = (const float*)d_in[3];
    const float* norm1_g  = (const float*)d_in[4];
    const float* norm1_b  = (const float*)d_in[5];
    const float* in_proj_w= (const float*)d_in[6];

    const float *convf_w, *convf_b, *convb_w, *convb_b;
    const float *xprojf_w, *xprojb_w, *dtf_w, *dtf_b, *dtb_w, *dtb_b;
    const float *A_log_f, *A_log_b, *D_f, *D_b;
    const float *mnorm_g, *mnorm_b, *outproj_w, *pnorm_g, *pnorm_b;
    const float *projback_w, *projback_b, *cw_w, *cw_b, *cwln_g, *cwln_b;

    if (in_sizes[9] == 2048) {
        // reference-signature order
        convf_w    = (const float*)d_in[7];
        convf_b    = (const float*)d_in[8];
        convb_w    = (const float*)d_in[9];
        convb_b    = (const float*)d_in[10];
        xprojf_w   = (const float*)d_in[11];
        xprojb_w   = (const float*)d_in[12];
        dtf_w      = (const float*)d_in[13];
        dtf_b      = (const float*)d_in[14];
        dtb_w      = (const float*)d_in[15];
        dtb_b      = (const float*)d_in[16];
        A_log_f    = (const float*)d_in[17];
        A_log_b    = (const float*)d_in[18];
        D_f        = (const float*)d_in[19];
        D_b        = (const float*)d_in[20];
    } else {
        // setup_inputs dict-insertion order (confirmed on HW)
        convf_w    = (const float*)d_in[7];
        convf_b    = (const float*)d_in[8];
        xprojf_w   = (const float*)d_in[9];
        dtf_w      = (const float*)d_in[10];
        dtf_b      = (const float*)d_in[11];
        A_log_f    = (const float*)d_in[12];
        D_f        = (const float*)d_in[13];
        convb_w    = (const float*)d_in[14];
        convb_b    = (const float*)d_in[15];
        xprojb_w   = (const float*)d_in[16];
        dtb_w      = (const float*)d_in[17];
        dtb_b      = (const float*)d_in[18];
        A_log_b    = (const float*)d_in[19];
        D_b        = (const float*)d_in[20];
    }
    mnorm_g    = (const float*)d_in[21];
    mnorm_b    = (const float*)d_in[22];
    outproj_w  = (const float*)d_in[23];
    pnorm_g    = (const float*)d_in[24];
    pnorm_b    = (const float*)d_in[25];
    projback_w = (const float*)d_in[26];
    projback_b = (const float*)d_in[27];
    cw_w       = (const float*)d_in[28];
    cw_b       = (const float*)d_in[29];
    cwln_g     = (const float*)d_in[30];
    cwln_b     = (const float*)d_in[31];
    float* out = (float*)d_out;

    float *combined, *weight, *xz, *u0, *xdbl0, *xpart, *delta0, *ycomb, *o1n, *o2, *o1;
    cudaGetSymbolAddress((void**)&combined, g_combined);
    cudaGetSymbolAddress((void**)&weight,   g_weight);
    cudaGetSymbolAddress((void**)&xz,       g_xz);
    cudaGetSymbolAddress((void**)&u0,       g_u);
    cudaGetSymbolAddress((void**)&xdbl0,    g_xdbl);
    cudaGetSymbolAddress((void**)&xpart,    g_xpart);
    cudaGetSymbolAddress((void**)&delta0,   g_delta);
    cudaGetSymbolAddress((void**)&ycomb,    g_ycomb);
    cudaGetSymbolAddress((void**)&o1n,      g_o1n);
    cudaGetSymbolAddress((void**)&o2,       g_o2);
    cudaGetSymbolAddress((void**)&o1,       g_o1);
    float* u1     = u0     + (size_t)TT*DI;
    float* xdbl1  = xdbl0  + (size_t)TT*64;
    float* xpart0 = xpart;
    float* xpart1 = xpart  + (size_t)4*TT*64;
    float* delta1 = delta0 + (size_t)TT*DI;

    // 1. input LayerNorms -> combined, x0n
    k_ln_inputs<<<TT, 256>>>(input0, input1, norm0_g, norm0_b, norm1_g, norm1_b);

    // 2. cw GEMM: (4096x512)@(256x512)^T + bias
    k_gemm<128,64,16,8,8,1><<<dim3(CC/64, TT/128), 128>>>(combined, DM, cw_w, DM, cw_b, weight, CC, DM);
    // 3. cw LN + sigmoid + clip
    k_cwln<<<TT, 256>>>(cwln_g, cwln_b);

    // 4. in_proj GEMM: (4096x512)@(1024x512)^T
    k_gemm<128,64,16,8,8,0><<<dim3(1024/64, TT/128), 128>>>(combined, DM, in_proj_w, DM, nullptr, xz, 1024, DM);

    // 5. conv + silu, both directions
    k_conv<<<dim3(LL/CONV_CHUNK, BB, 2), 512>>>(convf_w, convf_b, convb_w, convb_b);

    // 6. x_dbl GEMMs via split-K (4 slices of 128), then reduce
    k_gemm_part<128,64,16,8,8><<<dim3(1, TT/128, 4), 128>>>(u0, DI, xprojf_w, DI, xpart0, 64, 128);
    k_gemm_part<128,64,16,8,8><<<dim3(1, TT/128, 4), 128>>>(u1, DI, xprojb_w, DI, xpart1, 64, 128);
    k_xreduce<<<2*TT*64/256, 256>>>();

    // 7. delta GEMMs: (4096x32)@(512x32)^T + bias, softplus
    k_gemm<128,64,16,8,8,2><<<dim3(DI/64, TT/128), 128>>>(xdbl0, 64, dtf_w, DR, dtf_b, delta0, DI, DR);
    k_gemm<128,64,16,8,8,2><<<dim3(DI/64, TT/128), 128>>>(xdbl1, 64, dtb_w, DR, dtb_b, delta1, DI, DR);

    // 8. selective scan (both dirs), incl. D*u and silu(z) gate
    k_scan<<<128, 256>>>(A_log_f, A_log_b, D_f, D_b);

    // 9. combine + mnorm
    k_combine<<<TT, 512>>>(mnorm_g, mnorm_b);

    // 10. out_proj GEMM: (4096x512)@(512x512)^T
    k_gemm<128,64,16,8,8,0><<<dim3(DM/64, TT/128), 128>>>(ycomb, DI, outproj_w, DI, nullptr, o1, DM, DI);

    // 11. pnorm
    k_pnorm<<<TT, 512>>>(pnorm_g, pnorm_b);

    // 12. projback GEMM: (4096x512)@(256x512)^T + bias
    k_gemm<128,64,16,8,8,1><<<dim3(CC/64, TT/128), 128>>>(o1n, DM, projback_w, DM, projback_b, o2, CC, DM);

    // 13. final blend
    k_final<<<TT, 256>>>(input0, out);
}

// round 6
// speedup vs baseline: 2.0091x; 1.0605x over previous
#include <cuda_runtime.h>
#include <cuda_bf16.h>
#include <cstdint>
#include <cstddef>

// Problem constants
#define BB 4
#define LL 1024
#define CC 256
#define DM 512      // d_model
#define DI 512      // d_inner
#define DS 16       // d_state
#define DR 32       // dt_rank
#define TT (BB*LL)  // 4096 tokens

// ---------------- scratch (__device__ globals: allocation-free) ----------------
__device__ float g_combined[TT*DM];        // (t, 512)
__device__ float g_x0n[TT*CC];             // normalized input0
__device__ float g_weight[TT*CC];          // cw preact -> gate weight
__device__ float g_xz[TT*1024];            // (b,l,e) e in [0,1024)
__device__ float g_u[2][TT*DI];            // conv+silu output, scan-time coords
__device__ float g_xdbl[2][TT*64];         // dt|B|C per token
__device__ float g_xpart[2][4][TT*64];     // split-K partials for xproj
__device__ float g_delta[2][TT*DI];
__device__ float g_y[2][TT*DI];
__device__ float g_ycomb[TT*DI];
__device__ float g_o1[TT*DI];
__device__ float g_o1n[TT*DI];
__device__ float g_o2[TT*CC];
// bf16 split buffers (reused sequentially)
__device__ __nv_bfloat16 g_ah[TT*DM];
__device__ __nv_bfloat16 g_al[TT*DM];
__device__ __nv_bfloat16 g_wh[1024*DM];
__device__ __nv_bfloat16 g_wl[1024*DM];

// ---------------- helpers ----------------
__device__ __forceinline__ float cleanf(float x) {
    if (isnan(x)) return 0.f;
    if (isinf(x)) return x > 0.f ? 1.f : -1.f;
    return x;
}

__device__ __forceinline__ float siluf(float x) {
    return x / (1.f + __expf(-x));
}

template<int NW>
__device__ __forceinline__ float2 blockReduce2(float a, float b, float* sm) {
    __syncthreads();
    const unsigned full = 0xffffffffu;
    #pragma unroll
    for (int o = 16; o > 0; o >>= 1) {
        a += __shfl_xor_sync(full, a, o);
        b += __shfl_xor_sync(full, b, o);
    }
    int w = threadIdx.x >> 5, ln = threadIdx.x & 31;
    if (ln == 0) { sm[w] = a; sm[NW + w] = b; }
    __syncthreads();
    if (threadIdx.x < 32) {
        a = (ln < NW) ? sm[ln] : 0.f;
        b = (ln < NW) ? sm[NW + ln] : 0.f;
        #pragma unroll
        for (int o = 16; o > 0; o >>= 1) {
            a += __shfl_xor_sync(full, a, o);
            b += __shfl_xor_sync(full, b, o);
        }
        if (ln == 0) { sm[0] = a; sm[1] = b; }
    }
    __syncthreads();
    return make_float2(sm[0], sm[1]);
}

// ---------------- kernel 1: nan_to_num + LN(input0), LN(input1) -> combined ----------------
__global__ void k_ln_inputs(const float* __restrict__ i0, const float* __restrict__ i1,
                            const float* __restrict__ g0, const float* __restrict__ b0,
                            const float* __restrict__ g1, const float* __restrict__ b1) {
    __shared__ float sm[32];
    int t = blockIdx.x, c = threadIdx.x;
    float v0 = cleanf(i0[t*CC + c]);
    float v1 = cleanf(i1[t*CC + c]);
    float2 s0 = blockReduce2<8>(v0, v0*v0, sm);
    float m0 = s0.x * (1.f/CC);
    float var0 = s0.y * (1.f/CC) - m0*m0;
    float x0 = (v0 - m0) * rsqrtf(var0 + 1e-5f) * g0[c] + b0[c];
    g_x0n[t*CC + c] = x0;
    g_combined[t*DM + c] = x0;
    float2 s1 = blockReduce2<8>(v1, v1*v1, sm);
    float m1 = s1.x * (1.f/CC);
    float var1 = s1.y * (1.f/CC) - m1*m1;
    float x1 = (v1 - m1) * rsqrtf(var1 + 1e-5f) * g1[c] + b1[c];
    g_combined[t*DM + CC + c] = x1;
}

// ---------------- bf16 split: x -> hi + lo ----------------
__global__ void k_split(const float* __restrict__ x, __nv_bfloat16* __restrict__ h,
                        __nv_bfloat16* __restrict__ l, int n) {
    int i = (blockIdx.x * blockDim.x + threadIdx.x) * 4;
    if (i >= n) return;
    float4 v = *reinterpret_cast<const float4*>(x + i);
    const float* vp = &v.x;
    #pragma unroll
    for (int j = 0; j < 4; j++) {
        __nv_bfloat16 hi = __float2bfloat16(vp[j]);
        __nv_bfloat16 lo = __float2bfloat16(vp[j] - __bfloat162float(hi));
        h[i+j] = hi;
        l[i+j] = lo;
    }
}

// ---------------- tensor-core GEMM (bf16 split, 3 passes, fp32 acc) ----------------
// C[M,N] = A[M,K] * W[N,K]^T, A/W given as (hi, lo) bf16 pairs.
// Block 128x64, 8 warps (4x2), warp tile 32x32, mma m16n8k16.
__device__ __forceinline__ void mma16816(float c[4], const uint32_t a[4], const uint32_t b[2]) {
    asm volatile("mma.sync.aligned.m16n8k16.row.col.f32.bf16.bf16.f32 "
        "{%0,%1,%2,%3}, {%4,%5,%6,%7}, {%8,%9}, {%0,%1,%2,%3};"
        : "+f"(c[0]), "+f"(c[1]), "+f"(c[2]), "+f"(c[3])
        : "r"(a[0]), "r"(a[1]), "r"(a[2]), "r"(a[3]), "r"(b[0]), "r"(b[1]));
}

template<int EPI>   // 0 = none, 1 = +bias
__global__ void __launch_bounds__(256)
k_gemm_bf16(const __nv_bfloat16* __restrict__ Ah, const __nv_bfloat16* __restrict__ Al,
            const __nv_bfloat16* __restrict__ Wh, const __nv_bfloat16* __restrict__ Wl,
            const float* __restrict__ bias, float* __restrict__ C, int ldc, int K) {
    constexpr int BM = 128, BN = 64, BK = 32;
    constexpr int STR = 80;   // bytes per smem row: 64B data + 16B pad (conflict-free frag LDS)
    __shared__ __align__(16) unsigned char Asb[BM*STR];
    __shared__ __align__(16) unsigned char Wsb[BN*STR];
    const int tid = threadIdx.x;
    const int wid = tid >> 5, lane = tid & 31;
    const int warp_m = (wid >> 1) * 32;
    const int warp_n = (wid & 1) * 32;
    const int m0 = blockIdx.y * BM;
    const int n0 = blockIdx.x * BN;

    float c[2][4][4];
    #pragma unroll
    for (int i = 0; i < 2; i++)
        #pragma unroll
        for (int j = 0; j < 4; j++)
            #pragma unroll
            for (int q = 0; q < 4; q++) c[i][j][q] = 0.f;

    #pragma unroll 1
    for (int pass = 0; pass < 3; pass++) {
        const __nv_bfloat16* Ap = (pass == 1) ? Al : Ah;
        const __nv_bfloat16* Wp = (pass == 2) ? Wl : Wh;
        #pragma unroll 1
        for (int k0 = 0; k0 < K; k0 += BK) {
            __syncthreads();
            // fill A: 128x32 bf16 (512 16B-chunks, 2 per thread)
            #pragma unroll
            for (int f = tid; f < BM*BK/8; f += 256) {
                int m = f >> 2, kq = (f & 3) * 8;
                uint4 v = *reinterpret_cast<const uint4*>(Ap + (size_t)(m0+m)*K + k0 + kq);
                *reinterpret_cast<uint4*>(Asb + m*STR + kq*2) = v;
            }
            // fill W: 64x32 bf16 (256 chunks, 1 per thread)
            {
                int n = tid >> 2, kq = (tid & 3) * 8;
                uint4 v = *reinterpret_cast<const uint4*>(Wp + (size_t)(n0+n)*K + k0 + kq);
                *reinterpret_cast<uint4*>(Wsb + n*STR + kq*2) = v;
            }
            __syncthreads();
            #pragma unroll
            for (int kk = 0; kk < 2; kk++) {
                const int kb = kk * 16;
                uint32_t a[2][4];
                #pragma unroll
                for (int mf = 0; mf < 2; mf++) {
                    int r = warp_m + mf*16 + (lane >> 2);
                    int kc = kb + (lane & 3) * 2;
                    const unsigned char* p = Asb + r*STR + kc*2;
                    a[mf][0] = *reinterpret_cast<const uint32_t*>(p);
                    a[mf][1] = *reinterpret_cast<const uint32_t*>(p + 8*STR);
                    a[mf][2] = *reinterpret_cast<const uint32_t*>(p + 16);
                    a[mf][3] = *reinterpret_cast<const uint32_t*>(p + 8*STR + 16);
                }
                uint32_t b[4][2];
                #pragma unroll
                for (int nf = 0; nf < 4; nf++) {
                    int n = warp_n + nf*8 + (lane >> 2);
                    int kc = kb + (lane & 3) * 2;
                    const unsigned char* p = Wsb + n*STR + kc*2;
                    b[nf][0] = *reinterpret_cast<const uint32_t*>(p);
                    b[nf][1] = *reinterpret_cast<const uint32_t*>(p + 16);
                }
                #pragma unroll
                for (int mf = 0; mf < 2; mf++)
                    #pragma unroll
                    for (int nf = 0; nf < 4; nf++)
                        mma16816(c[mf][nf], a[mf], b[nf]);
            }
        }
    }

    // epilogue: c0:(r,col) c1:(r,col+1) c2:(r+8,col) c3:(r+8,col+1)
    #pragma unroll
    for (int mf = 0; mf < 2; mf++) {
        #pragma unroll
        for (int nf = 0; nf < 4; nf++) {
            int row = m0 + warp_m + mf*16 + (lane >> 2);
            int col = n0 + warp_n + nf*8 + (lane & 3)*2;
            float v0 = c[mf][nf][0], v1 = c[mf][nf][1];
            float v2 = c[mf][nf][2], v3 = c[mf][nf][3];
            if (EPI == 1) {
                float b0 = bias[col], b1 = bias[col+1];
                v0 += b0; v1 += b1; v2 += b0; v3 += b1;
            }
            *reinterpret_cast<float2*>(&C[(size_t)row*ldc + col]) = make_float2(v0, v1);
            *reinterpret_cast<float2*>(&C[(size_t)(row+8)*ldc + col]) = make_float2(v2, v3);
        }
    }
}

// ---------------- SIMT SGEMM (kept for dt / split-K xproj) ----------------
// EPI: 0 = store, 1 = +bias, 2 = +bias then softplus
template<int BM, int BN, int BK, int TM, int TN, int EPI>
__global__ void __launch_bounds__((BM/TM)*(BN/TN))
k_gemm(const float* __restrict__ A, int lda,
       const float* __restrict__ W, int ldw,
       const float* __restrict__ bias,
       float* __restrict__ C, int ldc, int K) {
    constexpr int THREADS = (BM/TM)*(BN/TN);
    __shared__ __align__(16) float As[BK][BM + 4];
    __shared__ __align__(16) float Ws[BK][BN + 4];
    const int tid = threadIdx.x;
    const int m0 = blockIdx.y * BM;
    const int n0 = blockIdx.x * BN;
    const int tn = (tid % (BN/TN)) * TN;
    const int tm = (tid / (BN/TN)) * TM;

    float acc[TM][TN];
    #pragma unroll
    for (int i = 0; i < TM; i++)
        #pragma unroll
        for (int j = 0; j < TN; j++) acc[i][j] = 0.f;

    constexpr int A4 = BM*BK/4;
    constexpr int W4 = BN*BK/4;

    for (int k0 = 0; k0 < K; k0 += BK) {
        __syncthreads();
        #pragma unroll
        for (int f = tid; f < A4; f += THREADS) {
            int m = f / (BK/4), kq = f % (BK/4);
            float4 v = *reinterpret_cast<const float4*>(&A[(size_t)(m0+m)*lda + k0 + kq*4]);
            As[kq*4+0][m] = v.x; As[kq*4+1][m] = v.y;
            As[kq*4+2][m] = v.z; As[kq*4+3][m] = v.w;
        }
        #pragma unroll
        for (int f = tid; f < W4; f += THREADS) {
            int n = f / (BK/4), kq = f % (BK/4);
            float4 v = *reinterpret_cast<const float4*>(&W[(size_t)(n0+n)*ldw + k0 + kq*4]);
            Ws[kq*4+0][n] = v.x; Ws[kq*4+1][n] = v.y;
            Ws[kq*4+2][n] = v.z; Ws[kq*4+3][n] = v.w;
        }
        __syncthreads();
        #pragma unroll
        for (int kk = 0; kk < BK; kk++) {
            float ra[TM], rw[TN];
            #pragma unroll
            for (int i = 0; i < TM; i += 4)
                *reinterpret_cast<float4*>(&ra[i]) =
                    *reinterpret_cast<const float4*>(&As[kk][tm + i]);
            #pragma unroll
            for (int j = 0; j < TN; j += 4)
                *reinterpret_cast<float4*>(&rw[j]) =
                    *reinterpret_cast<const float4*>(&Ws[kk][tn + j]);
            #pragma unroll
            for (int i = 0; i < TM; i++)
                #pragma unroll
                for (int j = 0; j < TN; j++)
                    acc[i][j] = fmaf(ra[i], rw[j], acc[i][j]);
        }
    }

    #pragma unroll
    for (int i = 0; i < TM; i++) {
        #pragma unroll
        for (int j0 = 0; j0 < TN; j0 += 4) {
            float4 v;
            float* vp = &v.x;
            #pragma unroll
            for (int j = 0; j < 4; j++) {
                float x = acc[i][j0+j];
                if (EPI >= 1) x += bias[n0 + tn + j0 + j];
                if (EPI == 2) x = (x > 20.f) ? x : log1pf(__expf(x));
                vp[j] = x;
            }
            *reinterpret_cast<float4*>(&C[(size_t)(m0 + tm + i)*ldc + n0 + tn + j0]) = v;
        }
    }
}

// ---------------- split-K partial GEMM for xproj ----------------
template<int BM, int BN, int BK, int TM, int TN>
__global__ void __launch_bounds__((BM/TM)*(BN/TN))
k_gemm_part(const float* __restrict__ A, int lda,
            const float* __restrict__ W, int ldw,
            float* __restrict__ P, int ldc, int Kslice) {
    constexpr int THREADS = (BM/TM)*(BN/TN);
    __shared__ __align__(16) float As[BK][BM + 4];
    __shared__ __align__(16) float Ws[BK][BN + 4];
    const int tid = threadIdx.x;
    const int m0 = blockIdx.y * BM;
    const int n0 = blockIdx.x * BN;
    const int s  = blockIdx.z;
    const int kb = s * Kslice;
    const int tn = (tid % (BN/TN)) * TN;
    const int tm = (tid / (BN/TN)) * TM;
    float* Pout = P + (size_t)s * (TT*64);

    float acc[TM][TN];
    #pragma unroll
    for (int i = 0; i < TM; i++)
        #pragma unroll
        for (int j = 0; j < TN; j++) acc[i][j] = 0.f;

    constexpr int A4 = BM*BK/4;
    constexpr int W4 = BN*BK/4;

    for (int k0 = kb; k0 < kb + Kslice; k0 += BK) {
        __syncthreads();
        #pragma unroll
        for (int f = tid; f < A4; f += THREADS) {
            int m = f / (BK/4), kq = f % (BK/4);
            float4 v = *reinterpret_cast<const float4*>(&A[(size_t)(m0+m)*lda + k0 + kq*4]);
            As[kq*4+0][m] = v.x; As[kq*4+1][m] = v.y;
            As[kq*4+2][m] = v.z; As[kq*4+3][m] = v.w;
        }
        #pragma unroll
        for (int f = tid; f < W4; f += THREADS) {
            int n = f / (BK/4), kq = f % (BK/4);
            float4 v = *reinterpret_cast<const float4*>(&W[(size_t)(n0+n)*ldw + k0 + kq*4]);
            Ws[kq*4+0][n] = v.x; Ws[kq*4+1][n] = v.y;
            Ws[kq*4+2][n] = v.z; Ws[kq*4+3][n] = v.w;
        }
        __syncthreads();
        #pragma unroll
        for (int kk = 0; kk < BK; kk++) {
            float ra[TM], rw[TN];
            #pragma unroll
            for (int i = 0; i < TM; i += 4)
                *reinterpret_cast<float4*>(&ra[i]) =
                    *reinterpret_cast<const float4*>(&As[kk][tm + i]);
            #pragma unroll
            for (int j = 0; j < TN; j += 4)
                *reinterpret_cast<float4*>(&rw[j]) =
                    *reinterpret_cast<const float4*>(&Ws[kk][tn + j]);
            #pragma unroll
            for (int i = 0; i < TM; i++)
                #pragma unroll
                for (int j = 0; j < TN; j++)
                    acc[i][j] = fmaf(ra[i], rw[j], acc[i][j]);
        }
    }

    #pragma unroll
    for (int i = 0; i < TM; i++)
        #pragma unroll
        for (int j0 = 0; j0 < TN; j0 += 4) {
            float4 v = make_float4(acc[i][j0], acc[i][j0+1], acc[i][j0+2], acc[i][j0+3]);
            *reinterpret_cast<float4*>(&Pout[(size_t)(m0 + tm + i)*ldc + n0 + tn + j0]) = v;
        }
}

__global__ void k_xreduce() {
    int i = blockIdx.x * blockDim.x + threadIdx.x;
    int dir = (i >= TT*64) ? 1 : 0;
    int j = i - dir * (TT*64);
    float s = (g_xpart[dir][0][j] + g_xpart[dir][1][j])
            + (g_xpart[dir][2][j] + g_xpart[dir][3][j]);
    g_xdbl[dir][j] = s;
}

// ---------------- LN(cwln) + sigmoid + clip ----------------
__global__ void k_cwln(const float* __restrict__ g, const float* __restrict__ b) {
    __shared__ float sm[32];
    int t = blockIdx.x, c = threadIdx.x;
    float v = g_weight[t*CC + c];
    float2 s = blockReduce2<8>(v, v*v, sm);
    float m = s.x * (1.f/CC);
    float var = s.y * (1.f/CC) - m*m;
    float x = (v - m) * rsqrtf(var + 1e-5f) * g[c] + b[c];
    float w = 1.f / (1.f + __expf(-x));
    w = fminf(fmaxf(w, 0.01f), 0.99f);
    g_weight[t*CC + c] = w;
}

// ---------------- depthwise causal conv + silu ----------------
#define CONV_CHUNK 64
__global__ void k_conv(const float* __restrict__ cwf, const float* __restrict__ cbf,
                       const float* __restrict__ cwb, const float* __restrict__ cbb) {
    int d = threadIdx.x;
    int b = blockIdx.y;
    int dir = blockIdx.z;
    int t0 = blockIdx.x * CONV_CHUNK;
    const float* w = dir ? cwb : cwf;
    float w0 = w[d*4+0], w1 = w[d*4+1], w2 = w[d*4+2], w3 = w[d*4+3];
    float bias = (dir ? cbb : cbf)[d];
    size_t base = (size_t)b * LL;

    auto fetch = [&](int t) -> float {
        if (t < 0) return 0.f;
        int l = dir ? (LL - 1 - t) : t;
        return g_xz[(base + l)*1024 + d];
    };

    float r0 = fetch(t0-3), r1 = fetch(t0-2), r2 = fetch(t0-1);
    float* uo = g_u[dir];
    #pragma unroll 4
    for (int i = 0; i < CONV_CHUNK; i++) {
        int t = t0 + i;
        float x3 = fetch(t);
        float accv = bias + w0*r0 + w1*r1 + w2*r2 + w3*x3;
        uo[(base + t)*DI + d] = siluf(accv);
        r0 = r1; r1 = r2; r2 = x3;
    }
}

// ---------------- selective scan ----------------
__global__ void k_scan(const float* __restrict__ Alf, const float* __restrict__ Alb,
                       const float* __restrict__ Df,  const float* __restrict__ Db) {
    int gid = blockIdx.x * blockDim.x + threadIdx.x;
    int l   = gid & 7;
    int d   = (gid >> 3) & 511;
    int b   = (gid >> 12) & 3;
    int dir = (gid >> 14) & 1;
    const unsigned full = 0xffffffffu;

    const float* Al = dir ? Alb : Alf;
    float a0 = -__expf(Al[d*DS + l*2 + 0]);
    float a1 = -__expf(Al[d*DS + l*2 + 1]);
    float Dv = (dir ? Db : Df)[d];

    const float* dl = g_delta[dir];
    const float* uu = g_u[dir];
    const float* xd = g_xdbl[dir];
    float* yo = g_y[dir];

    size_t base = (size_t)b * LL;
    float h0 = 0.f, h1 = 0.f;

    float  cd[4], cu[4], cz[4];
    float2 cB[4], cC[4];
    #pragma unroll
    for (int j = 0; j < 4; j++) {
        size_t row = base + j;
        cd[j] = dl[row*DI + d];
        cu[j] = uu[row*DI + d];
        cB[j] = *reinterpret_cast<const float2*>(xd + row*64 + 32 + l*2);
        cC[j] = *reinterpret_cast<const float2*>(xd + row*64 + 48 + l*2);
        int lq = dir ? (LL - 1 - j) : j;
        cz[j] = g_xz[(base + lq)*1024 + DI + d];
    }

    for (int t0 = 0; t0 < LL; t0 += 4) {
        float  nd[4] = {0,0,0,0}, nu[4] = {0,0,0,0}, nz[4] = {0,0,0,0};
        float2 nB[4] = {}, nC[4] = {};
        if (t0 + 4 < LL) {
            #pragma unroll
            for (int j = 0; j < 4; j++) {
                size_t row = base + t0 + 4 + j;
                nd[j] = dl[row*DI + d];
                nu[j] = uu[row*DI + d];
                nB[j] = *reinterpret_cast<const float2*>(xd + row*64 + 32 + l*2);
                nC[j] = *reinterpret_cast<const float2*>(xd + row*64 + 48 + l*2);
                int lq = dir ? (LL - 1 - (t0 + 4 + j)) : (t0 + 4 + j);
                nz[j] = g_xz[(base + lq)*1024 + DI + d];
            }
        }
        #pragma unroll
        for (int j = 0; j < 4; j++) {
            int t = t0 + j;
            float delta = cd[j], u = cu[j];
            float du = delta * u;
            h0 = fmaf(__expf(delta * a0), h0, du * cB[j].x);
            h1 = fmaf(__expf(delta * a1), h1, du * cB[j].y);
            float y = h0 * cC[j].x + h1 * cC[j].y;
            y += __shfl_xor_sync(full, y, 1);
            y += __shfl_xor_sync(full, y, 2);
            y += __shfl_xor_sync(full, y, 4);
            y = fmaf(Dv, u, y);
            y *= siluf(cz[j]);
            if (l == 0) yo[(base + t)*DI + d] = y;
        }
        #pragma unroll
        for (int j = 0; j < 4; j++) {
            cd[j] = nd[j]; cu[j] = nu[j]; cz[j] = nz[j];
            cB[j] = nB[j]; cC[j] = nC[j];
        }
    }
}

// ---------------- combine directions + mnorm LN ----------------
__global__ void k_combine(const float* __restrict__ g, const float* __restrict__ b_) {
    __shared__ float sm[32];
    int t = blockIdx.x;
    int b = t >> 10, l = t & (LL - 1);
    int d = threadIdx.x;
    float v = 0.5f * (g_y[0][(size_t)t*DI + d] +
                      g_y[1][((size_t)b*LL + (LL - 1 - l))*DI + d]);
    float2 s = blockReduce2<16>(v, v*v, sm);
    float m = s.x * (1.f/DI);
    float var = s.y * (1.f/DI) - m*m;
    g_ycomb[(size_t)t*DI + d] = (v - m) * rsqrtf(var + 1e-5f) * g[d] + b_[d];
}

// ---------------- pnorm LN ----------------
__global__ void k_pnorm(const float* __restrict__ g, const float* __restrict__ b) {
    __shared__ float sm[32];
    int t = blockIdx.x, d = threadIdx.x;
    float v = g_o1[(size_t)t*DM + d];
    float2 s = blockReduce2<16>(v, v*v, sm);
    float m = s.x * (1.f/DM);
    float var = s.y * (1.f/DM) - m*m;
    g_o1n[(size_t)t*DM + d] = (v - m) * rsqrtf(var + 1e-5f) * g[d] + b[d];
}

// ---------------- final blend ----------------
__global__ void k_final(const float* __restrict__ i0, float* __restrict__ out) {
    int idx = blockIdx.x * blockDim.x + threadIdx.x;
    float v = cleanf(g_o2[idx]);
    float w = g_weight[idx];
    out[idx] = v*w + g_x0n[idx]*(1.f - w) + cleanf(i0[idx]);
}

// ---------------- launch ----------------
extern "C" void kernel_launch(void* const* d_in, const int* in_sizes, int n_in,
                              void* d_out, int out_size) {
    const float* input0   = (const float*)d_in[0];
    const float* input1   = (const float*)d_in[1];
    const float* norm0_g  = (const float*)d_in[2];
    const float* norm0_b  = (const float*)d_in[3];
    const float* norm1_g  = (const float*)d_in[4];
    const float* norm1_b  = (const float*)d_in[5];
    const float* in_proj_w= (const float*)d_in[6];

    const float *convf_w, *convf_b, *convb_w, *convb_b;
    const float *xprojf_w, *xprojb_w, *dtf_w, *dtf_b, *dtb_w, *dtb_b;
    const float *A_log_f, *A_log_b, *D_f, *D_b;
    const float *mnorm_g, *mnorm_b, *outproj_w, *pnorm_g, *pnorm_b;
    const float *projback_w, *projback_b, *cw_w, *cw_b, *cwln_g, *cwln_b;

    if (in_sizes[9] == 2048) {
        convf_w    = (const float*)d_in[7];
        convf_b    = (const float*)d_in[8];
        convb_w    = (const float*)d_in[9];
        convb_b    = (const float*)d_in[10];
        xprojf_w   = (const float*)d_in[11];
        xprojb_w   = (const float*)d_in[12];
        dtf_w      = (const float*)d_in[13];
        dtf_b      = (const float*)d_in[14];
        dtb_w      = (const float*)d_in[15];
        dtb_b      = (const float*)d_in[16];
        A_log_f    = (const float*)d_in[17];
        A_log_b    = (const float*)d_in[18];
        D_f        = (const float*)d_in[19];
        D_b        = (const float*)d_in[20];
    } else {
        // setup_inputs dict-insertion order (confirmed on HW)
        convf_w    = (const float*)d_in[7];
        convf_b    = (const float*)d_in[8];
        xprojf_w   = (const float*)d_in[9];
        dtf_w      = (const float*)d_in[10];
        dtf_b      = (const float*)d_in[11];
        A_log_f    = (const float*)d_in[12];
        D_f        = (const float*)d_in[13];
        convb_w    = (const float*)d_in[14];
        convb_b    = (const float*)d_in[15];
        xprojb_w   = (const float*)d_in[16];
        dtb_w      = (const float*)d_in[17];
        dtb_b      = (const float*)d_in[18];
        A_log_b    = (const float*)d_in[19];
        D_b        = (const float*)d_in[20];
    }
    mnorm_g    = (const float*)d_in[21];
    mnorm_b    = (const float*)d_in[22];
    outproj_w  = (const float*)d_in[23];
    pnorm_g    = (const float*)d_in[24];
    pnorm_b    = (const float*)d_in[25];
    projback_w = (const float*)d_in[26];
    projback_b = (const float*)d_in[27];
    cw_w       = (const float*)d_in[28];
    cw_b       = (const float*)d_in[29];
    cwln_g     = (const float*)d_in[30];
    cwln_b     = (const float*)d_in[31];
    float* out = (float*)d_out;

    float *combined, *weight, *xz, *u0, *xdbl0, *xpart, *delta0, *ycomb, *o1n, *o2, *o1;
    __nv_bfloat16 *ah, *al, *wh, *wl;
    cudaGetSymbolAddress((void**)&combined, g_combined);
    cudaGetSymbolAddress((void**)&weight,   g_weight);
    cudaGetSymbolAddress((void**)&xz,       g_xz);
    cudaGetSymbolAddress((void**)&u0,       g_u);
    cudaGetSymbolAddress((void**)&xdbl0,    g_xdbl);
    cudaGetSymbolAddress((void**)&xpart,    g_xpart);
    cudaGetSymbolAddress((void**)&delta0,   g_delta);
    cudaGetSymbolAddress((void**)&ycomb,    g_ycomb);
    cudaGetSymbolAddress((void**)&o1n,      g_o1n);
    cudaGetSymbolAddress((void**)&o2,       g_o2);
    cudaGetSymbolAddress((void**)&o1,       g_o1);
    cudaGetSymbolAddress((void**)&ah,       g_ah);
    cudaGetSymbolAddress((void**)&al,       g_al);
    cudaGetSymbolAddress((void**)&wh,       g_wh);
    cudaGetSymbolAddress((void**)&wl,       g_wl);
    float* u1     = u0     + (size_t)TT*DI;
    float* xdbl1  = xdbl0  + (size_t)TT*64;
    float* xpart0 = xpart;
    float* xpart1 = xpart  + (size_t)4*TT*64;
    float* delta1 = delta0 + (size_t)TT*DI;

    const int SP = 256;   // split kernel threads

    // 1. input LayerNorms -> combined, x0n
    k_ln_inputs<<<TT, 256>>>(input0, input1, norm0_g, norm0_b, norm1_g, norm1_b);

    // 2a. split A (combined) once for cw + in_proj
    k_split<<<(TT*DM/4 + SP-1)/SP, SP>>>(combined, ah, al, TT*DM);

    // 2b. cw GEMM (bf16 tensor): (4096x512)@(256x512)^T + bias
    k_split<<<(CC*DM/4 + SP-1)/SP, SP>>>(cw_w, wh, wl, CC*DM);
    k_gemm_bf16<1><<<dim3(CC/64, TT/128), 256>>>(ah, al, wh, wl, cw_b, weight, CC, DM);
    // 3. cw LN + sigmoid + clip
    k_cwln<<<TT, 256>>>(cwln_g, cwln_b);

    // 4. in_proj GEMM (bf16 tensor): (4096x512)@(1024x512)^T
    k_split<<<(1024*DM/4 + SP-1)/SP, SP>>>(in_proj_w, wh, wl, 1024*DM);
    k_gemm_bf16<0><<<dim3(1024/64, TT/128), 256>>>(ah, al, wh, wl, nullptr, xz, 1024, DM);

    // 5. conv + silu, both directions
    k_conv<<<dim3(LL/CONV_CHUNK, BB, 2), 512>>>(convf_w, convf_b, convb_w, convb_b);

    // 6. x_dbl GEMMs via split-K (SIMT), then reduce
    k_gemm_part<128,64,16,8,8><<<dim3(1, TT/128, 4), 128>>>(u0, DI, xprojf_w, DI, xpart0, 64, 128);
    k_gemm_part<128,64,16,8,8><<<dim3(1, TT/128, 4), 128>>>(u1, DI, xprojb_w, DI, xpart1, 64, 128);
    k_xreduce<<<2*TT*64/256, 256>>>();

    // 7. delta GEMMs (SIMT): (4096x32)@(512x32)^T + bias, softplus
    k_gemm<128,64,16,8,8,2><<<dim3(DI/64, TT/128), 128>>>(xdbl0, 64, dtf_w, DR, dtf_b, delta0, DI, DR);
    k_gemm<128,64,16,8,8,2><<<dim3(DI/64, TT/128), 128>>>(xdbl1, 64, dtb_w, DR, dtb_b, delta1, DI, DR);

    // 8. selective scan
    k_scan<<<128, 256>>>(A_log_f, A_log_b, D_f, D_b);

    // 9. combine + mnorm
    k_combine<<<TT, 512>>>(mnorm_g, mnorm_b);

    // 10. out_proj GEMM (bf16 tensor): (4096x512)@(512x512)^T
    k_split<<<(TT*DI/4 + SP-1)/SP, SP>>>(ycomb, ah, al, TT*DI);
    k_split<<<(DM*DI/4 + SP-1)/SP, SP>>>(outproj_w, wh, wl, DM*DI);
    k_gemm_bf16<0><<<dim3(DM/64, TT/128), 256>>>(ah, al, wh, wl, nullptr, o1, DM, DI);

    // 11. pnorm
    k_pnorm<<<TT, 512>>>(pnorm_g, pnorm_b);

    // 12. projback GEMM (bf16 tensor): (4096x512)@(256x512)^T + bias
    k_split<<<(TT*DM/4 + SP-1)/SP, SP>>>(o1n, ah, al, TT*DM);
    k_split<<<(CC*DM/4 + SP-1)/SP, SP>>>(projback_w, wh, wl, CC*DM);
    k_gemm_bf16<1><<<dim3(CC/64, TT/128), 256>>>(ah, al, wh, wl, projback_b, o2, CC, DM);

    // 13. final blend
    k_final<<<TT, 256>>>(input0, out);
}

// round 8
// speedup vs baseline: 2.4404x; 1.2147x over previous
#include <cuda_runtime.h>
#include <cuda_bf16.h>
#include <cstdint>
#include <cstddef>

// Problem constants
#define BB 4
#define LL 1024
#define CC 256
#define DM 512      // d_model
#define DI 512      // d_inner
#define DS 16       // d_state
#define DR 32       // dt_rank
#define TT (BB*LL)  // 4096 tokens

// ---------------- scratch (__device__ globals: allocation-free) ----------------
__device__ float g_x0n[TT*CC];             // normalized input0
__device__ float g_weight[TT*CC];          // cw preact -> gate weight
__device__ float g_xz[TT*1024];            // (b,l,e) e in [0,1024)
__device__ float g_u[2][TT*DI];            // conv+silu output
__device__ float g_xdbl[2][TT*64];         // dt|B|C per token
__device__ float g_xpart[2][4][TT*64];     // split-K partials for xproj
__device__ float g_delta[2][TT*DI];
__device__ float g_y[2][TT*DI];
__device__ float g_o1[TT*DI];
__device__ float g_o2[TT*CC];
// bf16 activation split (reused: combined -> ycomb -> o1n)
__device__ __align__(16) __nv_bfloat16 g_abh[TT*DM];
__device__ __align__(16) __nv_bfloat16 g_abl[TT*DM];
// bf16 weight splits
__device__ __align__(16) __nv_bfloat16 g_cwh[CC*DM],   g_cwl[CC*DM];
__device__ __align__(16) __nv_bfloat16 g_iph[1024*DM], g_ipl[1024*DM];
__device__ __align__(16) __nv_bfloat16 g_oph[DM*DI],   g_opl[DM*DI];
__device__ __align__(16) __nv_bfloat16 g_pbh[CC*DM],   g_pbl[CC*DM];

// ---------------- helpers ----------------
__device__ __forceinline__ float cleanf(float x) {
    if (isnan(x)) return 0.f;
    if (isinf(x)) return x > 0.f ? 1.f : -1.f;
    return x;
}
__device__ __forceinline__ float siluf(float x) {
    return x / (1.f + __expf(-x));
}
__device__ __forceinline__ void split1(float x, __nv_bfloat16& h, __nv_bfloat16& l) {
    h = __float2bfloat16(x);
    l = __float2bfloat16(x - __bfloat162float(h));
}

template<int NW>
__device__ __forceinline__ float2 blockReduce2(float a, float b, float* sm) {
    __syncthreads();
    const unsigned full = 0xffffffffu;
    #pragma unroll
    for (int o = 16; o > 0; o >>= 1) {
        a += __shfl_xor_sync(full, a, o);
        b += __shfl_xor_sync(full, b, o);
    }
    int w = threadIdx.x >> 5, ln = threadIdx.x & 31;
    if (ln == 0) { sm[w] = a; sm[NW + w] = b; }
    __syncthreads();
    if (threadIdx.x < 32) {
        a = (ln < NW) ? sm[ln] : 0.f;
        b = (ln < NW) ? sm[NW + ln] : 0.f;
        #pragma unroll
        for (int o = 16; o > 0; o >>= 1) {
            a += __shfl_xor_sync(full, a, o);
            b += __shfl_xor_sync(full, b, o);
        }
        if (ln == 0) { sm[0] = a; sm[1] = b; }
    }
    __syncthreads();
    return make_float2(sm[0], sm[1]);
}

// ---------------- kernel 1: nan_to_num + LN inputs -> bf16 split of combined ----------------
__global__ void k_ln_inputs(const float* __restrict__ i0, const float* __restrict__ i1,
                            const float* __restrict__ g0, const float* __restrict__ b0,
                            const float* __restrict__ g1, const float* __restrict__ b1) {
    __shared__ float sm[32];
    int t = blockIdx.x, c = threadIdx.x;
    float v0 = cleanf(i0[t*CC + c]);
    float v1 = cleanf(i1[t*CC + c]);
    float2 s0 = blockReduce2<8>(v0, v0*v0, sm);
    float m0 = s0.x * (1.f/CC);
    float var0 = s0.y * (1.f/CC) - m0*m0;
    float x0 = (v0 - m0) * rsqrtf(var0 + 1e-5f) * g0[c] + b0[c];
    g_x0n[t*CC + c] = x0;
    split1(x0, g_abh[t*DM + c], g_abl[t*DM + c]);
    float2 s1 = blockReduce2<8>(v1, v1*v1, sm);
    float m1 = s1.x * (1.f/CC);
    float var1 = s1.y * (1.f/CC) - m1*m1;
    float x1 = (v1 - m1) * rsqrtf(var1 + 1e-5f) * g1[c] + b1[c];
    split1(x1, g_abh[t*DM + CC + c], g_abl[t*DM + CC + c]);
}

// ---------------- weight split: all four weight matrices in one kernel ----------------
__global__ void k_split_w(const float* __restrict__ cw, const float* __restrict__ ip,
                          const float* __restrict__ op, const float* __restrict__ pb) {
    int v = blockIdx.x * blockDim.x + threadIdx.x;   // vec4 index, 262144 total
    const float* src; __nv_bfloat16 *h, *l; int off;
    if (v < 32768)        { src = cw; h = g_cwh; l = g_cwl; off = v; }
    else if (v < 163840)  { src = ip; h = g_iph; l = g_ipl; off = v - 32768; }
    else if (v < 229376)  { src = op; h = g_oph; l = g_opl; off = v - 163840; }
    else                  { src = pb; h = g_pbh; l = g_pbl; off = v - 229376; }
    float4 x = *reinterpret_cast<const float4*>(src + (size_t)off*4);
    const float* xp = &x.x;
    #pragma unroll
    for (int j = 0; j < 4; j++) split1(xp[j], h[off*4 + j], l[off*4 + j]);
}

// ---------------- cp.async helpers ----------------
__device__ __forceinline__ void cpa16(void* dst, const void* src) {
    uint32_t s = (uint32_t)__cvta_generic_to_shared(dst);
    asm volatile("cp.async.cg.shared.global [%0], [%1], 16;\n" :: "r"(s), "l"(src));
}
__device__ __forceinline__ void cp_commit() { asm volatile("cp.async.commit_group;\n"); }
__device__ __forceinline__ void cp_wait0()  { asm volatile("cp.async.wait_group 0;\n"); }
__device__ __forceinline__ void cp_wait1()  { asm volatile("cp.async.wait_group 1;\n"); }

__device__ __forceinline__ void mma16816(float c[4], const uint32_t a[4], const uint32_t b[2]) {
    asm volatile("mma.sync.aligned.m16n8k16.row.col.f32.bf16.bf16.f32 "
        "{%0,%1,%2,%3}, {%4,%5,%6,%7}, {%8,%9}, {%0,%1,%2,%3};"
        : "+f"(c[0]), "+f"(c[1]), "+f"(c[2]), "+f"(c[3])
        : "r"(a[0]), "r"(a[1]), "r"(a[2]), "r"(a[3]), "r"(b[0]), "r"(b[1]));
}

// ---------------- tensor-core GEMM: fused 3-term bf16 split, cp.async 2-stage ----------------
// C[M,N] = A[M,K] * W[N,K]^T ~= Ah*Wh + Al*Wh + Ah*Wl.  BN=64, BK=16.
// BM=128 -> 256 thr (8 warps 4x2); BM=64 -> 128 thr (4 warps 2x2). Warp tile 32x32.
template<int BM, int EPI>
__global__ void __launch_bounds__(BM == 128 ? 256 : 128)
k_gemm_bf16(const __nv_bfloat16* __restrict__ Ah, const __nv_bfloat16* __restrict__ Al,
            const __nv_bfloat16* __restrict__ Wh, const __nv_bfloat16* __restrict__ Wl,
            const float* __restrict__ bias, float* __restrict__ C, int ldc, int K) {
    constexpr int THREADS = (BM == 128) ? 256 : 128;
    constexpr int STR = 48;   // bytes/row: 32B data + 16B pad
    __shared__ __align__(16) unsigned char sAh[2][BM*STR];
    __shared__ __align__(16) unsigned char sAl[2][BM*STR];
    __shared__ __align__(16) unsigned char sWh[2][64*STR];
    __shared__ __align__(16) unsigned char sWl[2][64*STR];
    const int tid = threadIdx.x;
    const int wid = tid >> 5, lane = tid & 31;
    const int warp_m = (wid >> 1) * 32;
    const int warp_n = (wid & 1) * 32;
    const int m0 = blockIdx.y * BM;
    const int n0 = blockIdx.x * 64;

    float c[2][4][4];
    #pragma unroll
    for (int i = 0; i < 2; i++)
        #pragma unroll
        for (int j = 0; j < 4; j++)
            #pragma unroll
            for (int q = 0; q < 4; q++) c[i][j][q] = 0.f;

    auto load_stage = [&](int s, int k0) {
        #pragma unroll
        for (int f = tid; f < BM*2; f += THREADS) {
            int m = f >> 1, hh = f & 1;
            size_t go = (size_t)(m0 + m)*K + k0 + hh*8;
            cpa16(&sAh[s][m*STR + hh*16], Ah + go);
            cpa16(&sAl[s][m*STR + hh*16], Al + go);
        }
        #pragma unroll
        for (int f = tid; f < 128; f += THREADS) {
            int n = f >> 1, hh = f & 1;
            size_t go = (size_t)(n0 + n)*K + k0 + hh*8;
            cpa16(&sWh[s][n*STR + hh*16], Wh + go);
            cpa16(&sWl[s][n*STR + hh*16], Wl + go);
        }
    };

    const int NK = K / 16;
    load_stage(0, 0);
    cp_commit();

    for (int ks = 0; ks < NK; ks++) {
        int cur = ks & 1;
        if (ks + 1 < NK) {
            load_stage(1 - cur, (ks + 1) * 16);
            cp_commit();
            cp_wait1();
        } else {
            cp_wait0();
        }
        __syncthreads();

        const unsigned char* Ahb = sAh[cur];
        const unsigned char* Alb = sAl[cur];
        const unsigned char* Whb = sWh[cur];
        const unsigned char* Wlb = sWl[cur];

        uint32_t fah[2][4], fal[2][4];
        #pragma unroll
        for (int mf = 0; mf < 2; mf++) {
            int r = warp_m + mf*16 + (lane >> 2);
            const unsigned char* p = Ahb + r*STR + (lane & 3)*4;
            const unsigned char* q = Alb + r*STR + (lane & 3)*4;
            fah[mf][0] = *reinterpret_cast<const uint32_t*>(p);
            fah[mf][1] = *reinterpret_cast<const uint32_t*>(p + 8*STR);
            fah[mf][2] = *reinterpret_cast<const uint32_t*>(p + 16);
            fah[mf][3] = *reinterpret_cast<const uint32_t*>(p + 8*STR + 16);
            fal[mf][0] = *reinterpret_cast<const uint32_t*>(q);
            fal[mf][1] = *reinterpret_cast<const uint32_t*>(q + 8*STR);
            fal[mf][2] = *reinterpret_cast<const uint32_t*>(q + 16);
            fal[mf][3] = *reinterpret_cast<const uint32_t*>(q + 8*STR + 16);
        }
        uint32_t fbh[4][2], fbl[4][2];
        #pragma unroll
        for (int nf = 0; nf < 4; nf++) {
            int n = warp_n + nf*8 + (lane >> 2);
            const unsigned char* p = Whb + n*STR + (lane & 3)*4;
            const unsigned char* q = Wlb + n*STR + (lane & 3)*4;
            fbh[nf][0] = *reinterpret_cast<const uint32_t*>(p);
            fbh[nf][1] = *reinterpret_cast<const uint32_t*>(p + 16);
            fbl[nf][0] = *reinterpret_cast<const uint32_t*>(q);
            fbl[nf][1] = *reinterpret_cast<const uint32_t*>(q + 16);
        }
        #pragma unroll
        for (int mf = 0; mf < 2; mf++)
            #pragma unroll
            for (int nf = 0; nf < 4; nf++) {
                mma16816(c[mf][nf], fah[mf], fbh[nf]);
                mma16816(c[mf][nf], fal[mf], fbh[nf]);
                mma16816(c[mf][nf], fah[mf], fbl[nf]);
            }
        __syncthreads();
    }

    #pragma unroll
    for (int mf = 0; mf < 2; mf++) {
        #pragma unroll
        for (int nf = 0; nf < 4; nf++) {
            int row = m0 + warp_m + mf*16 + (lane >> 2);
            int col = n0 + warp_n + nf*8 + (lane & 3)*2;
            float v0 = c[mf][nf][0], v1 = c[mf][nf][1];
            float v2 = c[mf][nf][2], v3 = c[mf][nf][3];
            if (EPI == 1) {
                float b0 = bias[col], b1 = bias[col+1];
                v0 += b0; v1 += b1; v2 += b0; v3 += b1;
            }
            *reinterpret_cast<float2*>(&C[(size_t)row*ldc + col]) = make_float2(v0, v1);
            *reinterpret_cast<float2*>(&C[(size_t)(row+8)*ldc + col]) = make_float2(v2, v3);
        }
    }
}

// ---------------- SIMT SGEMM (dt GEMMs) ----------------
template<int BM, int BN, int BK, int TM, int TN, int EPI>
__global__ void __launch_bounds__((BM/TM)*(BN/TN))
k_gemm(const float* __restrict__ A, int lda,
       const float* __restrict__ W, int ldw,
       const float* __restrict__ bias,
       float* __restrict__ C, int ldc, int K) {
    constexpr int THREADS = (BM/TM)*(BN/TN);
    __shared__ __align__(16) float As[BK][BM + 4];
    __shared__ __align__(16) float Ws[BK][BN + 4];
    const int tid = threadIdx.x;
    const int m0 = blockIdx.y * BM;
    const int n0 = blockIdx.x * BN;
    const int tn = (tid % (BN/TN)) * TN;
    const int tm = (tid / (BN/TN)) * TM;

    float acc[TM][TN];
    #pragma unroll
    for (int i = 0; i < TM; i++)
        #pragma unroll
        for (int j = 0; j < TN; j++) acc[i][j] = 0.f;

    constexpr int A4 = BM*BK/4;
    constexpr int W4 = BN*BK/4;

    for (int k0 = 0; k0 < K; k0 += BK) {
        __syncthreads();
        #pragma unroll
        for (int f = tid; f < A4; f += THREADS) {
            int m = f / (BK/4), kq = f % (BK/4);
            float4 v = *reinterpret_cast<const float4*>(&A[(size_t)(m0+m)*lda + k0 + kq*4]);
            As[kq*4+0][m] = v.x; As[kq*4+1][m] = v.y;
            As[kq*4+2][m] = v.z; As[kq*4+3][m] = v.w;
        }
        #pragma unroll
        for (int f = tid; f < W4; f += THREADS) {
            int n = f / (BK/4), kq = f % (BK/4);
            float4 v = *reinterpret_cast<const float4*>(&W[(size_t)(n0+n)*ldw + k0 + kq*4]);
            Ws[kq*4+0][n] = v.x; Ws[kq*4+1][n] = v.y;
            Ws[kq*4+2][n] = v.z; Ws[kq*4+3][n] = v.w;
        }
        __syncthreads();
        #pragma unroll
        for (int kk = 0; kk < BK; kk++) {
            float ra[TM], rw[TN];
            #pragma unroll
            for (int i = 0; i < TM; i += 4)
                *reinterpret_cast<float4*>(&ra[i]) =
                    *reinterpret_cast<const float4*>(&As[kk][tm + i]);
            #pragma unroll
            for (int j = 0; j < TN; j += 4)
                *reinterpret_cast<float4*>(&rw[j]) =
                    *reinterpret_cast<const float4*>(&Ws[kk][tn + j]);
            #pragma unroll
            for (int i = 0; i < TM; i++)
                #pragma unroll
                for (int j = 0; j < TN; j++)
                    acc[i][j] = fmaf(ra[i], rw[j], acc[i][j]);
        }
    }

    #pragma unroll
    for (int i = 0; i < TM; i++) {
        #pragma unroll
        for (int j0 = 0; j0 < TN; j0 += 4) {
            float4 v;
            float* vp = &v.x;
            #pragma unroll
            for (int j = 0; j < 4; j++) {
                float x = acc[i][j0+j];
                if (EPI >= 1) x += bias[n0 + tn + j0 + j];
                if (EPI == 2) x = (x > 20.f) ? x : log1pf(__expf(x));
                vp[j] = x;
            }
            *reinterpret_cast<float4*>(&C[(size_t)(m0 + tm + i)*ldc + n0 + tn + j0]) = v;
        }
    }
}

// ---------------- split-K partial GEMM for xproj ----------------
template<int BM, int BN, int BK, int TM, int TN>
__global__ void __launch_bounds__((BM/TM)*(BN/TN))
k_gemm_part(const float* __restrict__ A, int lda,
            const float* __restrict__ W, int ldw,
            float* __restrict__ P, int ldc, int Kslice) {
    constexpr int THREADS = (BM/TM)*(BN/TN);
    __shared__ __align__(16) float As[BK][BM + 4];
    __shared__ __align__(16) float Ws[BK][BN + 4];
    const int tid = threadIdx.x;
    const int m0 = blockIdx.y * BM;
    const int n0 = blockIdx.x * BN;
    const int s  = blockIdx.z;
    const int kb = s * Kslice;
    const int tn = (tid % (BN/TN)) * TN;
    const int tm = (tid / (BN/TN)) * TM;
    float* Pout = P + (size_t)s * (TT*64);

    float acc[TM][TN];
    #pragma unroll
    for (int i = 0; i < TM; i++)
        #pragma unroll
        for (int j = 0; j < TN; j++) acc[i][j] = 0.f;

    constexpr int A4 = BM*BK/4;
    constexpr int W4 = BN*BK/4;

    for (int k0 = kb; k0 < kb + Kslice; k0 += BK) {
        __syncthreads();
        #pragma unroll
        for (int f = tid; f < A4; f += THREADS) {
            int m = f / (BK/4), kq = f % (BK/4);
            float4 v = *reinterpret_cast<const float4*>(&A[(size_t)(m0+m)*lda + k0 + kq*4]);
            As[kq*4+0][m] = v.x; As[kq*4+1][m] = v.y;
            As[kq*4+2][m] = v.z; As[kq*4+3][m] = v.w;
        }
        #pragma unroll
        for (int f = tid; f < W4; f += THREADS) {
            int n = f / (BK/4), kq = f % (BK/4);
            float4 v = *reinterpret_cast<const float4*>(&W[(size_t)(n0+n)*ldw + k0 + kq*4]);
            Ws[kq*4+0][n] = v.x; Ws[kq*4+1][n] = v.y;
            Ws[kq*4+2][n] = v.z; Ws[kq*4+3][n] = v.w;
        }
        __syncthreads();
        #pragma unroll
        for (int kk = 0; kk < BK; kk++) {
            float ra[TM], rw[TN];
            #pragma unroll
            for (int i = 0; i < TM; i += 4)
                *reinterpret_cast<float4*>(&ra[i]) =
                    *reinterpret_cast<const float4*>(&As[kk][tm + i]);
            #pragma unroll
            for (int j = 0; j < TN; j += 4)
                *reinterpret_cast<float4*>(&rw[j]) =
                    *reinterpret_cast<const float4*>(&Ws[kk][tn + j]);
            #pragma unroll
            for (int i = 0; i < TM; i++)
                #pragma unroll
                for (int j = 0; j < TN; j++)
                    acc[i][j] = fmaf(ra[i], rw[j], acc[i][j]);
        }
    }

    #pragma unroll
    for (int i = 0; i < TM; i++)
        #pragma unroll
        for (int j0 = 0; j0 < TN; j0 += 4) {
            float4 v = make_float4(acc[i][j0], acc[i][j0+1], acc[i][j0+2], acc[i][j0+3]);
            *reinterpret_cast<float4*>(&Pout[(size_t)(m0 + tm + i)*ldc + n0 + tn + j0]) = v;
        }
}

__global__ void k_xreduce() {
    int i = blockIdx.x * blockDim.x + threadIdx.x;
    int dir = (i >= TT*64) ? 1 : 0;
    int j = i - dir * (TT*64);
    float s = (g_xpart[dir][0][j] + g_xpart[dir][1][j])
            + (g_xpart[dir][2][j] + g_xpart[dir][3][j]);
    g_xdbl[dir][j] = s;
}

// ---------------- LN(cwln) + sigmoid + clip ----------------
__global__ void k_cwln(const float* __restrict__ g, const float* __restrict__ b) {
    __shared__ float sm[32];
    int t = blockIdx.x, c = threadIdx.x;
    float v = g_weight[t*CC + c];
    float2 s = blockReduce2<8>(v, v*v, sm);
    float m = s.x * (1.f/CC);
    float var = s.y * (1.f/CC) - m*m;
    float x = (v - m) * rsqrtf(var + 1e-5f) * g[c] + b[c];
    float w = 1.f / (1.f + __expf(-x));
    w = fminf(fmaxf(w, 0.01f), 0.99f);
    g_weight[t*CC + c] = w;
}

// ---------------- depthwise causal conv + silu ----------------
#define CONV_CHUNK 64
__global__ void k_conv(const float* __restrict__ cwf, const float* __restrict__ cbf,
                       const float* __restrict__ cwb, const float* __restrict__ cbb) {
    int d = threadIdx.x;
    int b = blockIdx.y;
    int dir = blockIdx.z;
    int t0 = blockIdx.x * CONV_CHUNK;
    const float* w = dir ? cwb : cwf;
    float w0 = w[d*4+0], w1 = w[d*4+1], w2 = w[d*4+2], w3 = w[d*4+3];
    float bias = (dir ? cbb : cbf)[d];
    size_t base = (size_t)b * LL;

    auto fetch = [&](int t) -> float {
        if (t < 0) return 0.f;
        int l = dir ? (LL - 1 - t) : t;
        return g_xz[(base + l)*1024 + d];
    };

    float r0 = fetch(t0-3), r1 = fetch(t0-2), r2 = fetch(t0-1);
    float* uo = g_u[dir];
    #pragma unroll 4
    for (int i = 0; i < CONV_CHUNK; i++) {
        int t = t0 + i;
        float x3 = fetch(t);
        float accv = bias + w0*r0 + w1*r1 + w2*r2 + w3*x3;
        uo[(base + t)*DI + d] = siluf(accv);
        r0 = r1; r1 = r2; r2 = x3;
    }
}

// ---------------- selective scan ----------------
__global__ void k_scan(const float* __restrict__ Alf, const float* __restrict__ Alb,
                       const float* __restrict__ Df,  const float* __restrict__ Db) {
    int gid = blockIdx.x * blockDim.x + threadIdx.x;
    int l   = gid & 7;
    int d   = (gid >> 3) & 511;
    int b   = (gid >> 12) & 3;
    int dir = (gid >> 14) & 1;
    const unsigned full = 0xffffffffu;

    const float* Al = dir ? Alb : Alf;
    float a0 = -__expf(Al[d*DS + l*2 + 0]);
    float a1 = -__expf(Al[d*DS + l*2 + 1]);
    float Dv = (dir ? Db : Df)[d];

    const float* dl = g_delta[dir];
    const float* uu = g_u[dir];
    const float* xd = g_xdbl[dir];
    float* yo = g_y[dir];

    size_t base = (size_t)b * LL;
    float h0 = 0.f, h1 = 0.f;

    float  cd[4], cu[4], cz[4];
    float2 cB[4], cC[4];
    #pragma unroll
    for (int j = 0; j < 4; j++) {
        size_t row = base + j;
        cd[j] = dl[row*DI + d];
        cu[j] = uu[row*DI + d];
        cB[j] = *reinterpret_cast<const float2*>(xd + row*64 + 32 + l*2);
        cC[j] = *reinterpret_cast<const float2*>(xd + row*64 + 48 + l*2);
        int lq = dir ? (LL - 1 - j) : j;
        cz[j] = g_xz[(base + lq)*1024 + DI + d];
    }

    for (int t0 = 0; t0 < LL; t0 += 4) {
        float  nd[4] = {0,0,0,0}, nu[4] = {0,0,0,0}, nz[4] = {0,0,0,0};
        float2 nB[4] = {}, nC[4] = {};
        if (t0 + 4 < LL) {
            #pragma unroll
            for (int j = 0; j < 4; j++) {
                size_t row = base + t0 + 4 + j;
                nd[j] = dl[row*DI + d];
                nu[j] = uu[row*DI + d];
                nB[j] = *reinterpret_cast<const float2*>(xd + row*64 + 32 + l*2);
                nC[j] = *reinterpret_cast<const float2*>(xd + row*64 + 48 + l*2);
                int lq = dir ? (LL - 1 - (t0 + 4 + j)) : (t0 + 4 + j);
                nz[j] = g_xz[(base + lq)*1024 + DI + d];
            }
        }
        #pragma unroll
        for (int j = 0; j < 4; j++) {
            int t = t0 + j;
            float delta = cd[j], u = cu[j];
            float du = delta * u;
            h0 = fmaf(__expf(delta * a0), h0, du * cB[j].x);
            h1 = fmaf(__expf(delta * a1), h1, du * cB[j].y);
            float y = h0 * cC[j].x + h1 * cC[j].y;
            y += __shfl_xor_sync(full, y, 1);
            y += __shfl_xor_sync(full, y, 2);
            y += __shfl_xor_sync(full, y, 4);
            y = fmaf(Dv, u, y);
            y *= siluf(cz[j]);
            if (l == 0) yo[(base + t)*DI + d] = y;
        }
        #pragma unroll
        for (int j = 0; j < 4; j++) {
            cd[j] = nd[j]; cu[j] = nu[j]; cz[j] = nz[j];
            cB[j] = nB[j]; cC[j] = nC[j];
        }
    }
}

// ---------------- combine directions + mnorm LN -> bf16 split ----------------
__global__ void k_combine(const float* __restrict__ g, const float* __restrict__ b_) {
    __shared__ float sm[32];
    int t = blockIdx.x;
    int b = t >> 10, l = t & (LL - 1);
    int d = threadIdx.x;
    float v = 0.5f * (g_y[0][(size_t)t*DI + d] +
                      g_y[1][((size_t)b*LL + (LL - 1 - l))*DI + d]);
    float2 s = blockReduce2<16>(v, v*v, sm);
    float m = s.x * (1.f/DI);
    float var = s.y * (1.f/DI) - m*m;
    float x = (v - m) * rsqrtf(var + 1e-5f) * g[d] + b_[d];
    split1(x, g_abh[(size_t)t*DI + d], g_abl[(size_t)t*DI + d]);
}

// ---------------- pnorm LN -> bf16 split ----------------
__global__ void k_pnorm(const float* __restrict__ g, const float* __restrict__ b) {
    __shared__ float sm[32];
    int t = blockIdx.x, d = threadIdx.x;
    float v = g_o1[(size_t)t*DM + d];
    float2 s = blockReduce2<16>(v, v*v, sm);
    float m = s.x * (1.f/DM);
    float var = s.y * (1.f/DM) - m*m;
    float x = (v - m) * rsqrtf(var + 1e-5f) * g[d] + b[d];
    split1(x, g_abh[(size_t)t*DM + d], g_abl[(size_t)t*DM + d]);
}

// ---------------- final blend ----------------
__global__ void k_final(const float* __restrict__ i0, float* __restrict__ out) {
    int idx = blockIdx.x * blockDim.x + threadIdx.x;
    float v = cleanf(g_o2[idx]);
    float w = g_weight[idx];
    out[idx] = v*w + g_x0n[idx]*(1.f - w) + cleanf(i0[idx]);
}

// ---------------- launch ----------------
extern "C" void kernel_launch(void* const* d_in, const int* in_sizes, int n_in,
                              void* d_out, int out_size) {
    const float* input0   = (const float*)d_in[0];
    const float* input1   = (const float*)d_in[1];
    const float* norm0_g  = (const float*)d_in[2];
    const float* norm0_b  = (const float*)d_in[3];
    const float* norm1_g  = (const float*)d_in[4];
    const float* norm1_b  = (const float*)d_in[5];
    const float* in_proj_w= (const float*)d_in[6];

    const float *convf_w, *convf_b, *convb_w, *convb_b;
    const float *xprojf_w, *xprojb_w, *dtf_w, *dtf_b, *dtb_w, *dtb_b;
    const float *A_log_f, *A_log_b, *D_f, *D_b;
    const float *mnorm_g, *mnorm_b, *outproj_w, *pnorm_g, *pnorm_b;
    const float *projback_w, *projback_b, *cw_w, *cw_b, *cwln_g, *cwln_b;

    if (in_sizes[9] == 2048) {
        convf_w    = (const float*)d_in[7];
        convf_b    = (const float*)d_in[8];
        convb_w    = (const float*)d_in[9];
        convb_b    = (const float*)d_in[10];
        xprojf_w   = (const float*)d_in[11];
        xprojb_w   = (const float*)d_in[12];
        dtf_w      = (const float*)d_in[13];
        dtf_b      = (const float*)d_in[14];
        dtb_w      = (const float*)d_in[15];
        dtb_b      = (const float*)d_in[16];
        A_log_f    = (const float*)d_in[17];
        A_log_b    = (const float*)d_in[18];
        D_f        = (const float*)d_in[19];
        D_b        = (const float*)d_in[20];
    } else {
        // setup_inputs dict-insertion order (confirmed on HW)
        convf_w    = (const float*)d_in[7];
        convf_b    = (const float*)d_in[8];
        xprojf_w   = (const float*)d_in[9];
        dtf_w      = (const float*)d_in[10];
        dtf_b      = (const float*)d_in[11];
        A_log_f    = (const float*)d_in[12];
        D_f        = (const float*)d_in[13];
        convb_w    = (const float*)d_in[14];
        convb_b    = (const float*)d_in[15];
        xprojb_w   = (const float*)d_in[16];
        dtb_w      = (const float*)d_in[17];
        dtb_b      = (const float*)d_in[18];
        A_log_b    = (const float*)d_in[19];
        D_b        = (const float*)d_in[20];
    }
    mnorm_g    = (const float*)d_in[21];
    mnorm_b    = (const float*)d_in[22];
    outproj_w  = (const float*)d_in[23];
    pnorm_g    = (const float*)d_in[24];
    pnorm_b    = (const float*)d_in[25];
    projback_w = (const float*)d_in[26];
    projback_b = (const float*)d_in[27];
    cw_w       = (const float*)d_in[28];
    cw_b       = (const float*)d_in[29];
    cwln_g     = (const float*)d_in[30];
    cwln_b     = (const float*)d_in[31];
    float* out = (float*)d_out;

    float *weight, *xz, *u0, *xdbl0, *xpart, *delta0, *o1, *o2;
    __nv_bfloat16 *abh, *abl, *cwh, *cwl, *iph, *ipl, *oph, *opl, *pbh, *pbl;
    cudaGetSymbolAddress((void**)&weight,   g_weight);
    cudaGetSymbolAddress((void**)&xz,       g_xz);
    cudaGetSymbolAddress((void**)&u0,       g_u);
    cudaGetSymbolAddress((void**)&xdbl0,    g_xdbl);
    cudaGetSymbolAddress((void**)&xpart,    g_xpart);
    cudaGetSymbolAddress((void**)&delta0,   g_delta);
    cudaGetSymbolAddress((void**)&o1,       g_o1);
    cudaGetSymbolAddress((void**)&o2,       g_o2);
    cudaGetSymbolAddress((void**)&abh,      g_abh);
    cudaGetSymbolAddress((void**)&abl,      g_abl);
    cudaGetSymbolAddress((void**)&cwh,      g_cwh);
    cudaGetSymbolAddress((void**)&cwl,      g_cwl);
    cudaGetSymbolAddress((void**)&iph,      g_iph);
    cudaGetSymbolAddress((void**)&ipl,      g_ipl);
    cudaGetSymbolAddress((void**)&oph,      g_oph);
    cudaGetSymbolAddress((void**)&opl,      g_opl);
    cudaGetSymbolAddress((void**)&pbh,      g_pbh);
    cudaGetSymbolAddress((void**)&pbl,      g_pbl);
    float* u1     = u0     + (size_t)TT*DI;
    float* xdbl1  = xdbl0  + (size_t)TT*64;
    float* xpart0 = xpart;
    float* xpart1 = xpart  + (size_t)4*TT*64;
    float* delta1 = delta0 + (size_t)TT*DI;

    // 0. split all weights (one kernel)
    k_split_w<<<1024, 256>>>(cw_w, in_proj_w, outproj_w, projback_w);

    // 1. input LayerNorms -> x0n + bf16 split of combined
    k_ln_inputs<<<TT, 256>>>(input0, input1, norm0_g, norm0_b, norm1_g, norm1_b);

    // 2. cw GEMM (tensor): (4096x512)@(256x512)^T + bias
    k_gemm_bf16<64,1><<<dim3(CC/64, TT/64), 128>>>(abh, abl, cwh, cwl, cw_b, weight, CC, DM);
    // 3. cw LN + sigmoid + clip
    k_cwln<<<TT, 256>>>(cwln_g, cwln_b);

    // 4. in_proj GEMM (tensor): (4096x512)@(1024x512)^T
    k_gemm_bf16<128,0><<<dim3(1024/64, TT/128), 256>>>(abh, abl, iph, ipl, nullptr, xz, 1024, DM);

    // 5. conv + silu, both directions
    k_conv<<<dim3(LL/CONV_CHUNK, BB, 2), 512>>>(convf_w, convf_b, convb_w, convb_b);

    // 6. x_dbl GEMMs via split-K (SIMT), then reduce
    k_gemm_part<128,64,16,8,8><<<dim3(1, TT/128, 4), 128>>>(u0, DI, xprojf_w, DI, xpart0, 64, 128);
    k_gemm_part<128,64,16,8,8><<<dim3(1, TT/128, 4), 128>>>(u1, DI, xprojb_w, DI, xpart1, 64, 128);
    k_xreduce<<<2*TT*64/256, 256>>>();

    // 7. delta GEMMs (SIMT): (4096x32)@(512x32)^T + bias, softplus
    k_gemm<128,64,16,8,8,2><<<dim3(DI/64, TT/128), 128>>>(xdbl0, 64, dtf_w, DR, dtf_b, delta0, DI, DR);
    k_gemm<128,64,16,8,8,2><<<dim3(DI/64, TT/128), 128>>>(xdbl1, 64, dtb_w, DR, dtb_b, delta1, DI, DR);

    // 8. selective scan
    k_scan<<<128, 256>>>(A_log_f, A_log_b, D_f, D_b);

    // 9. combine + mnorm -> bf16 split
    k_combine<<<TT, 512>>>(mnorm_g, mnorm_b);

    // 10. out_proj GEMM (tensor): (4096x512)@(512x512)^T
    k_gemm_bf16<128,0><<<dim3(DM/64, TT/128), 256>>>(abh, abl, oph, opl, nullptr, o1, DM, DI);

    // 11. pnorm -> bf16 split
    k_pnorm<<<TT, 512>>>(pnorm_g, pnorm_b);

    // 12. projback GEMM (tensor): (4096x512)@(256x512)^T + bias
    k_gemm_bf16<64,1><<<dim3(CC/64, TT/64), 128>>>(abh, abl, pbh, pbl, projback_b, o2, CC, DM);

    // 13. final blend
    k_final<<<TT, 256>>>(input0, out);
}